// round 2
// baseline (speedup 1.0000x reference)
#include <cuda_runtime.h>
#include <cstdint>
#include <cstddef>

#define NUM_B   8
#define NUM_N   1024
#define NUM_H   8
#define DHEAD   64
#define DIN     512
#define DINNER  512
#define DOUT    512
#define QK_SCALE 0.125f
#define NEG_BIG (-1.0e30f)

// Scratch (allocation-free: device globals)
__device__ float g_q[NUM_B * NUM_H * NUM_N * DHEAD];
__device__ float g_k[NUM_B * NUM_H * NUM_N * DHEAD];
__device__ float g_v[NUM_B * NUM_H * NUM_N * DHEAD];
__device__ float g_att[NUM_B * NUM_N * DINNER];

// ---------------------------------------------------------------------------
// Kernel 1: fused QKV projection.  C[8192 x 1536] = x[8192 x 512] @ [Wq | Wkv]
// 128x128 tile, BK=16, 256 threads, 8x8 micro-tile, reg-prefetch.
// Epilogue scatters into q/k/v with [b,h,n,d] layout (float4).
// ---------------------------------------------------------------------------
__global__ __launch_bounds__(256) void qkv_gemm_kernel(
    const float* __restrict__ x,
    const float* __restrict__ Wq,
    const float* __restrict__ Wkv)
{
    __shared__ float As[16][132];   // [k][row]
    __shared__ float Bs[16][132];   // [k][col]

    const int tid  = threadIdx.x;
    const int tx   = tid & 15, ty = tid >> 4;
    const int row0 = blockIdx.y * 128;
    const int col0 = blockIdx.x * 128;

    const float* W; int wld, wc0;
    if (col0 < DINNER) { W = Wq;  wld = DINNER;     wc0 = col0; }
    else               { W = Wkv; wld = 2 * DINNER; wc0 = col0 - DINNER; }

    const int ar = tid >> 1, ac = (tid & 1) * 8;    // A: 128 rows x 16 k
    const int br = tid >> 4, bc = (tid & 15) * 8;   // B: 16 rows x 128 cols

    const float* ag = x + (size_t)(row0 + ar) * DIN + ac;
    const float* bg = W + (size_t)br * wld + wc0 + bc;

    float acc[8][8];
#pragma unroll
    for (int i = 0; i < 8; i++)
#pragma unroll
        for (int j = 0; j < 8; j++) acc[i][j] = 0.f;

    float4 ra0 = *reinterpret_cast<const float4*>(ag);
    float4 ra1 = *reinterpret_cast<const float4*>(ag + 4);
    float4 rb0 = *reinterpret_cast<const float4*>(bg);
    float4 rb1 = *reinterpret_cast<const float4*>(bg + 4);

    for (int k0 = 0; k0 < DIN; k0 += 16) {
        // stage to smem (A transposed)
        As[ac + 0][ar] = ra0.x; As[ac + 1][ar] = ra0.y;
        As[ac + 2][ar] = ra0.z; As[ac + 3][ar] = ra0.w;
        As[ac + 4][ar] = ra1.x; As[ac + 5][ar] = ra1.y;
        As[ac + 6][ar] = ra1.z; As[ac + 7][ar] = ra1.w;
        *reinterpret_cast<float4*>(&Bs[br][bc])     = rb0;
        *reinterpret_cast<float4*>(&Bs[br][bc + 4]) = rb1;
        __syncthreads();

        if (k0 + 16 < DIN) {
            ra0 = *reinterpret_cast<const float4*>(ag + k0 + 16);
            ra1 = *reinterpret_cast<const float4*>(ag + k0 + 20);
            rb0 = *reinterpret_cast<const float4*>(bg + (size_t)(k0 + 16) * wld);
            rb1 = *reinterpret_cast<const float4*>(bg + (size_t)(k0 + 16) * wld + 4);
        }

#pragma unroll
        for (int kk = 0; kk < 16; kk++) {
            float a[8], b[8];
            float4 t;
            t = *reinterpret_cast<const float4*>(&As[kk][ty * 8]);     a[0]=t.x; a[1]=t.y; a[2]=t.z; a[3]=t.w;
            t = *reinterpret_cast<const float4*>(&As[kk][ty * 8 + 4]); a[4]=t.x; a[5]=t.y; a[6]=t.z; a[7]=t.w;
            t = *reinterpret_cast<const float4*>(&Bs[kk][tx * 8]);     b[0]=t.x; b[1]=t.y; b[2]=t.z; b[3]=t.w;
            t = *reinterpret_cast<const float4*>(&Bs[kk][tx * 8 + 4]); b[4]=t.x; b[5]=t.y; b[6]=t.z; b[7]=t.w;
#pragma unroll
            for (int i = 0; i < 8; i++)
#pragma unroll
                for (int j = 0; j < 8; j++) acc[i][j] += a[i] * b[j];
        }
        __syncthreads();
    }

    // epilogue: 8 cols per thread are contiguous and stay within one head
    const int c0 = col0 + tx * 8;
    float* dst; int cc0;
    if (c0 < DINNER)          { dst = g_q; cc0 = c0; }
    else if (c0 < 2 * DINNER) { dst = g_k; cc0 = c0 - DINNER; }
    else                      { dst = g_v; cc0 = c0 - 2 * DINNER; }
    const int h = cc0 >> 6, d = cc0 & 63;
#pragma unroll
    for (int i = 0; i < 8; i++) {
        const int r  = row0 + ty * 8 + i;
        const int bb = r >> 10, n = r & 1023;
        float* p = dst + ((size_t)(bb * NUM_H + h) * NUM_N + n) * DHEAD + d;
        float4 w0 = make_float4(acc[i][0], acc[i][1], acc[i][2], acc[i][3]);
        float4 w1 = make_float4(acc[i][4], acc[i][5], acc[i][6], acc[i][7]);
        *reinterpret_cast<float4*>(p)     = w0;
        *reinterpret_cast<float4*>(p + 4) = w1;
    }
}

// ---------------------------------------------------------------------------
// Kernel 2: flash attention.  CTA = (h, i-block of 64 rows, b). 256 threads.
// All inner-loop smem traffic is LDS.128; V held transposed in smem.
// ---------------------------------------------------------------------------
__global__ __launch_bounds__(256) void attn_kernel(
    const float* __restrict__ sim_bias,
    const int*   __restrict__ mask)
{
    extern __shared__ float sm[];
    float* q_s  = sm;                 // 64*68
    float* k_s  = q_s + 64 * 68;      // 64*68
    float* v_t  = k_s + 64 * 68;      // 64*68  transposed: v_t[d][j]
    float* p_s  = v_t + 64 * 68;      // 64*68
    float* mk_s = p_s + 64 * 68;      // 64

    const int h  = blockIdx.x;
    const int i0 = blockIdx.y * 64;
    const int b  = blockIdx.z;
    const int tid = threadIdx.x;

    const float* qg = g_q + ((size_t)(b * NUM_H + h) * NUM_N + i0) * DHEAD;
    const float* kg = g_k + (size_t)(b * NUM_H + h) * NUM_N * DHEAD;
    const float* vg = g_v + (size_t)(b * NUM_H + h) * NUM_N * DHEAD;

    // load q tile (64x64), pad-68 rows
    {
        const int r = tid >> 2, cb = (tid & 3) * 16;
#pragma unroll
        for (int u = 0; u < 4; u++) {
            float4 t = *reinterpret_cast<const float4*>(qg + (size_t)r * 64 + cb + u * 4);
            *reinterpret_cast<float4*>(&q_s[r * 68 + cb + u * 4]) = t;
        }
    }

    const int lane = tid & 31;
    const int lr   = lane >> 3;       // 0..3
    const int ljg  = lane & 7;        // 0..7
    const int r0   = (tid >> 5) * 8;  // warp row base
    const int rowA = r0 + lr;
    const int rowB = r0 + lr + 4;

    float m0 = NEG_BIG, m1 = NEG_BIG;
    float l0 = 0.f, l1 = 0.f;
    float o[2][8];
#pragma unroll
    for (int dd = 0; dd < 8; dd++) { o[0][dd] = 0.f; o[1][dd] = 0.f; }

    for (int jt = 0; jt < 16; jt++) {
        const int j0 = jt * 64;
        // cooperative load: k (row-major pad68) and v transposed
        {
            const int r = tid >> 2, cb = (tid & 3) * 16;
#pragma unroll
            for (int u = 0; u < 4; u++) {
                float4 t = *reinterpret_cast<const float4*>(kg + (size_t)(j0 + r) * 64 + cb + u * 4);
                *reinterpret_cast<float4*>(&k_s[r * 68 + cb + u * 4]) = t;
                float4 tv = *reinterpret_cast<const float4*>(vg + (size_t)(j0 + r) * 64 + cb + u * 4);
                v_t[(cb + u * 4 + 0) * 68 + r] = tv.x;
                v_t[(cb + u * 4 + 1) * 68 + r] = tv.y;
                v_t[(cb + u * 4 + 2) * 68 + r] = tv.z;
                v_t[(cb + u * 4 + 3) * 68 + r] = tv.w;
            }
        }
        if (tid < 64) mk_s[tid] = mask[b * NUM_N + j0 + tid] ? 0.f : NEG_BIG;
        __syncthreads();

        // S = q @ k^T : per lane 2 rows x 8 cols, LDS.128 everywhere
        float s0[8], s1[8];
#pragma unroll
        for (int jj = 0; jj < 8; jj++) { s0[jj] = 0.f; s1[jj] = 0.f; }
#pragma unroll 4
        for (int kk = 0; kk < 64; kk += 4) {
            float4 qa = *reinterpret_cast<const float4*>(&q_s[rowA * 68 + kk]);
            float4 qb = *reinterpret_cast<const float4*>(&q_s[rowB * 68 + kk]);
#pragma unroll
            for (int jj = 0; jj < 8; jj++) {
                float4 kv = *reinterpret_cast<const float4*>(&k_s[(ljg * 8 + jj) * 68 + kk]);
                s0[jj] += qa.x * kv.x; s0[jj] += qa.y * kv.y;
                s0[jj] += qa.z * kv.z; s0[jj] += qa.w * kv.w;
                s1[jj] += qb.x * kv.x; s1[jj] += qb.y * kv.y;
                s1[jj] += qb.z * kv.z; s1[jj] += qb.w * kv.w;
            }
        }

        // scale + bias + mask; bias layout [b, i, j, h]
        const float* bA = sim_bias + (((size_t)b * NUM_N + (i0 + rowA)) * NUM_N + (j0 + ljg * 8)) * NUM_H + h;
        const float* bB = sim_bias + (((size_t)b * NUM_N + (i0 + rowB)) * NUM_N + (j0 + ljg * 8)) * NUM_H + h;
        float mt0 = NEG_BIG, mt1 = NEG_BIG;
#pragma unroll
        for (int jj = 0; jj < 8; jj++) {
            const float mm = mk_s[ljg * 8 + jj];
            s0[jj] = fmaf(s0[jj], QK_SCALE, __ldg(bA + jj * NUM_H) + mm);
            s1[jj] = fmaf(s1[jj], QK_SCALE, __ldg(bB + jj * NUM_H) + mm);
            mt0 = fmaxf(mt0, s0[jj]);
            mt1 = fmaxf(mt1, s1[jj]);
        }
#pragma unroll
        for (int off = 1; off < 8; off <<= 1) {
            mt0 = fmaxf(mt0, __shfl_xor_sync(0xffffffffu, mt0, off));
            mt1 = fmaxf(mt1, __shfl_xor_sync(0xffffffffu, mt1, off));
        }

        const float mn0 = fmaxf(m0, mt0), mn1 = fmaxf(m1, mt1);
        const float c0  = __expf(m0 - mn0), c1 = __expf(m1 - mn1);
        l0 *= c0; l1 *= c1;
#pragma unroll
        for (int dd = 0; dd < 8; dd++) { o[0][dd] *= c0; o[1][dd] *= c1; }

        float p0[8], p1[8];
        float rs0 = 0.f, rs1 = 0.f;
#pragma unroll
        for (int jj = 0; jj < 8; jj++) {
            p0[jj] = __expf(s0[jj] - mn0);
            p1[jj] = __expf(s1[jj] - mn1);
            rs0 += p0[jj]; rs1 += p1[jj];
        }
        *reinterpret_cast<float4*>(&p_s[rowA * 68 + ljg * 8])     = make_float4(p0[0], p0[1], p0[2], p0[3]);
        *reinterpret_cast<float4*>(&p_s[rowA * 68 + ljg * 8 + 4]) = make_float4(p0[4], p0[5], p0[6], p0[7]);
        *reinterpret_cast<float4*>(&p_s[rowB * 68 + ljg * 8])     = make_float4(p1[0], p1[1], p1[2], p1[3]);
        *reinterpret_cast<float4*>(&p_s[rowB * 68 + ljg * 8 + 4]) = make_float4(p1[4], p1[5], p1[6], p1[7]);
#pragma unroll
        for (int off = 1; off < 8; off <<= 1) {
            rs0 += __shfl_xor_sync(0xffffffffu, rs0, off);
            rs1 += __shfl_xor_sync(0xffffffffu, rs1, off);
        }
        l0 += rs0; l1 += rs1; m0 = mn0; m1 = mn1;
        __syncwarp();

        // O += P @ V   (lane owns d = dd*8 + ljg); LDS.128 over j
#pragma unroll 4
        for (int j = 0; j < 64; j += 4) {
            float4 pa = *reinterpret_cast<const float4*>(&p_s[rowA * 68 + j]);
            float4 pb = *reinterpret_cast<const float4*>(&p_s[rowB * 68 + j]);
#pragma unroll
            for (int dd = 0; dd < 8; dd++) {
                float4 vv = *reinterpret_cast<const float4*>(&v_t[(dd * 8 + ljg) * 68 + j]);
                o[0][dd] += pa.x * vv.x; o[0][dd] += pa.y * vv.y;
                o[0][dd] += pa.z * vv.z; o[0][dd] += pa.w * vv.w;
                o[1][dd] += pb.x * vv.x; o[1][dd] += pb.y * vv.y;
                o[1][dd] += pb.z * vv.z; o[1][dd] += pb.w * vv.w;
            }
        }
        __syncthreads();
    }

    const float inv0 = 1.f / l0, inv1 = 1.f / l1;
    float* oA = g_att + ((size_t)b * NUM_N + i0 + rowA) * DINNER + h * DHEAD;
    float* oB = g_att + ((size_t)b * NUM_N + i0 + rowB) * DINNER + h * DHEAD;
#pragma unroll
    for (int dd = 0; dd < 8; dd++) {
        oA[dd * 8 + ljg] = o[0][dd] * inv0;
        oB[dd * 8 + ljg] = o[1][dd] * inv1;
    }
}

// ---------------------------------------------------------------------------
// Kernel 3: output projection.  out[8192 x 512] = att @ Wout + bout
// Same 128x128 / 8x8 structure as kernel 1.
// ---------------------------------------------------------------------------
__global__ __launch_bounds__(256) void out_gemm_kernel(
    const float* __restrict__ Wout,
    const float* __restrict__ bout,
    float* __restrict__ out)
{
    __shared__ float As[16][132];
    __shared__ float Bs[16][132];

    const int tid  = threadIdx.x;
    const int tx   = tid & 15, ty = tid >> 4;
    const int row0 = blockIdx.y * 128;
    const int col0 = blockIdx.x * 128;

    const int ar = tid >> 1, ac = (tid & 1) * 8;
    const int br = tid >> 4, bc = (tid & 15) * 8;

    const float* ag = g_att + (size_t)(row0 + ar) * DINNER + ac;
    const float* bg = Wout + (size_t)br * DOUT + col0 + bc;

    float acc[8][8];
#pragma unroll
    for (int i = 0; i < 8; i++)
#pragma unroll
        for (int j = 0; j < 8; j++) acc[i][j] = 0.f;

    float4 ra0 = *reinterpret_cast<const float4*>(ag);
    float4 ra1 = *reinterpret_cast<const float4*>(ag + 4);
    float4 rb0 = *reinterpret_cast<const float4*>(bg);
    float4 rb1 = *reinterpret_cast<const float4*>(bg + 4);

    for (int k0 = 0; k0 < DINNER; k0 += 16) {
        As[ac + 0][ar] = ra0.x; As[ac + 1][ar] = ra0.y;
        As[ac + 2][ar] = ra0.z; As[ac + 3][ar] = ra0.w;
        As[ac + 4][ar] = ra1.x; As[ac + 5][ar] = ra1.y;
        As[ac + 6][ar] = ra1.z; As[ac + 7][ar] = ra1.w;
        *reinterpret_cast<float4*>(&Bs[br][bc])     = rb0;
        *reinterpret_cast<float4*>(&Bs[br][bc + 4]) = rb1;
        __syncthreads();

        if (k0 + 16 < DINNER) {
            ra0 = *reinterpret_cast<const float4*>(ag + k0 + 16);
            ra1 = *reinterpret_cast<const float4*>(ag + k0 + 20);
            rb0 = *reinterpret_cast<const float4*>(bg + (size_t)(k0 + 16) * DOUT);
            rb1 = *reinterpret_cast<const float4*>(bg + (size_t)(k0 + 16) * DOUT + 4);
        }

#pragma unroll
        for (int kk = 0; kk < 16; kk++) {
            float a[8], b[8];
            float4 t;
            t = *reinterpret_cast<const float4*>(&As[kk][ty * 8]);     a[0]=t.x; a[1]=t.y; a[2]=t.z; a[3]=t.w;
            t = *reinterpret_cast<const float4*>(&As[kk][ty * 8 + 4]); a[4]=t.x; a[5]=t.y; a[6]=t.z; a[7]=t.w;
            t = *reinterpret_cast<const float4*>(&Bs[kk][tx * 8]);     b[0]=t.x; b[1]=t.y; b[2]=t.z; b[3]=t.w;
            t = *reinterpret_cast<const float4*>(&Bs[kk][tx * 8 + 4]); b[4]=t.x; b[5]=t.y; b[6]=t.z; b[7]=t.w;
#pragma unroll
            for (int i = 0; i < 8; i++)
#pragma unroll
                for (int j = 0; j < 8; j++) acc[i][j] += a[i] * b[j];
        }
        __syncthreads();
    }

    const int c0 = col0 + tx * 8;
    float4 bv0 = *reinterpret_cast<const float4*>(bout + c0);
    float4 bv1 = *reinterpret_cast<const float4*>(bout + c0 + 4);
#pragma unroll
    for (int i = 0; i < 8; i++) {
        const int r = row0 + ty * 8 + i;
        float4 w0 = make_float4(acc[i][0] + bv0.x, acc[i][1] + bv0.y,
                                acc[i][2] + bv0.z, acc[i][3] + bv0.w);
        float4 w1 = make_float4(acc[i][4] + bv1.x, acc[i][5] + bv1.y,
                                acc[i][6] + bv1.z, acc[i][7] + bv1.w);
        *reinterpret_cast<float4*>(out + (size_t)r * DOUT + c0)     = w0;
        *reinterpret_cast<float4*>(out + (size_t)r * DOUT + c0 + 4) = w1;
    }
}

// ---------------------------------------------------------------------------
extern "C" void kernel_launch(void* const* d_in, const int* in_sizes, int n_in,
                              void* d_out, int out_size)
{
    const float* x    = (const float*)d_in[0];
    const int*   mask = (const int*)  d_in[1];
    const float* sb   = (const float*)d_in[2];
    const float* Wq   = (const float*)d_in[3];
    const float* Wkv  = (const float*)d_in[4];
    const float* Wout = (const float*)d_in[5];
    const float* bout = (const float*)d_in[6];
    float* out = (float*)d_out;

    // 1) QKV projection: 8192 x 1536 (12 x 64 tiles of 128x128)
    qkv_gemm_kernel<<<dim3(12, 64), 256>>>(x, Wq, Wkv);

    // 2) flash attention; h fastest in grid for bias L2 sector reuse across heads
    const int smem = (64 * 68 * 4 + 64) * (int)sizeof(float);  // ~68.3 KB
    cudaFuncSetAttribute(attn_kernel, cudaFuncAttributeMaxDynamicSharedMemorySize, smem);
    attn_kernel<<<dim3(NUM_H, NUM_N / 64, NUM_B), 256, smem>>>(sb, mask);

    // 3) output projection: 8192 x 512 (4 x 64 tiles of 128x128)
    out_gemm_kernel<<<dim3(4, 64), 256>>>(Wout, bout, out);
}

// round 3
// speedup vs baseline: 1.7245x; 1.7245x over previous
#include <cuda_runtime.h>
#include <cstdint>
#include <cstddef>

#define NUM_B   8
#define NUM_N   1024
#define NUM_H   8
#define DHEAD   64
#define DIN     512
#define DINNER  512
#define DOUT    512
#define QK_SCALE 0.125f
#define NEG_BIG (-1.0e30f)

// Scratch (allocation-free: device globals)
__device__ float g_q[NUM_B * NUM_H * NUM_N * DHEAD];
__device__ float g_k[NUM_B * NUM_H * NUM_N * DHEAD];
__device__ float g_v[NUM_B * NUM_H * NUM_N * DHEAD];
__device__ float g_att[NUM_B * NUM_N * DINNER];

// ---------------------------------------------------------------------------
// Kernel 1: fused QKV projection.  C[8192 x 1536] = x[8192 x 512] @ [Wq | Wkv]
// 128x128 tile, BK=16, 256 threads, 8x8 micro-tile, double-buffered smem
// (one __syncthreads per K-step).
// ---------------------------------------------------------------------------
__global__ __launch_bounds__(256) void qkv_gemm_kernel(
    const float* __restrict__ x,
    const float* __restrict__ Wq,
    const float* __restrict__ Wkv)
{
    __shared__ float As[2][16][132];   // [buf][k][row]
    __shared__ float Bs[2][16][132];   // [buf][k][col]

    const int tid  = threadIdx.x;
    const int tx   = tid & 15, ty = tid >> 4;
    const int row0 = blockIdx.y * 128;
    const int col0 = blockIdx.x * 128;

    const float* W; int wld, wc0;
    if (col0 < DINNER) { W = Wq;  wld = DINNER;     wc0 = col0; }
    else               { W = Wkv; wld = 2 * DINNER; wc0 = col0 - DINNER; }

    const int ar = tid >> 1, ac = (tid & 1) * 8;    // A: 128 rows x 16 k
    const int br = tid >> 4, bc = (tid & 15) * 8;   // B: 16 rows x 128 cols

    const float* ag = x + (size_t)(row0 + ar) * DIN + ac;
    const float* bg = W + (size_t)br * wld + wc0 + bc;

    float acc[8][8];
#pragma unroll
    for (int i = 0; i < 8; i++)
#pragma unroll
        for (int j = 0; j < 8; j++) acc[i][j] = 0.f;

    float4 ra0 = *reinterpret_cast<const float4*>(ag);
    float4 ra1 = *reinterpret_cast<const float4*>(ag + 4);
    float4 rb0 = *reinterpret_cast<const float4*>(bg);
    float4 rb1 = *reinterpret_cast<const float4*>(bg + 4);

    // stage k0=0 into buffer 0
    As[0][ac + 0][ar] = ra0.x; As[0][ac + 1][ar] = ra0.y;
    As[0][ac + 2][ar] = ra0.z; As[0][ac + 3][ar] = ra0.w;
    As[0][ac + 4][ar] = ra1.x; As[0][ac + 5][ar] = ra1.y;
    As[0][ac + 6][ar] = ra1.z; As[0][ac + 7][ar] = ra1.w;
    *reinterpret_cast<float4*>(&Bs[0][br][bc])     = rb0;
    *reinterpret_cast<float4*>(&Bs[0][br][bc + 4]) = rb1;
    __syncthreads();

    for (int k0 = 0; k0 < DIN; k0 += 16) {
        const int buf = (k0 >> 4) & 1;
        const bool more = (k0 + 16 < DIN);
        if (more) {
            ra0 = *reinterpret_cast<const float4*>(ag + k0 + 16);
            ra1 = *reinterpret_cast<const float4*>(ag + k0 + 20);
            rb0 = *reinterpret_cast<const float4*>(bg + (size_t)(k0 + 16) * wld);
            rb1 = *reinterpret_cast<const float4*>(bg + (size_t)(k0 + 16) * wld + 4);
        }

#pragma unroll
        for (int kk = 0; kk < 16; kk++) {
            float a[8], b[8];
            float4 t;
            t = *reinterpret_cast<const float4*>(&As[buf][kk][ty * 8]);     a[0]=t.x; a[1]=t.y; a[2]=t.z; a[3]=t.w;
            t = *reinterpret_cast<const float4*>(&As[buf][kk][ty * 8 + 4]); a[4]=t.x; a[5]=t.y; a[6]=t.z; a[7]=t.w;
            t = *reinterpret_cast<const float4*>(&Bs[buf][kk][tx * 8]);     b[0]=t.x; b[1]=t.y; b[2]=t.z; b[3]=t.w;
            t = *reinterpret_cast<const float4*>(&Bs[buf][kk][tx * 8 + 4]); b[4]=t.x; b[5]=t.y; b[6]=t.z; b[7]=t.w;
#pragma unroll
            for (int i = 0; i < 8; i++)
#pragma unroll
                for (int j = 0; j < 8; j++) acc[i][j] += a[i] * b[j];
        }

        if (more) {
            const int nb = buf ^ 1;
            As[nb][ac + 0][ar] = ra0.x; As[nb][ac + 1][ar] = ra0.y;
            As[nb][ac + 2][ar] = ra0.z; As[nb][ac + 3][ar] = ra0.w;
            As[nb][ac + 4][ar] = ra1.x; As[nb][ac + 5][ar] = ra1.y;
            As[nb][ac + 6][ar] = ra1.z; As[nb][ac + 7][ar] = ra1.w;
            *reinterpret_cast<float4*>(&Bs[nb][br][bc])     = rb0;
            *reinterpret_cast<float4*>(&Bs[nb][br][bc + 4]) = rb1;
            __syncthreads();
        }
    }

    // epilogue: 8 cols per thread are contiguous and stay within one head
    const int c0 = col0 + tx * 8;
    float* dst; int cc0;
    if (c0 < DINNER)          { dst = g_q; cc0 = c0; }
    else if (c0 < 2 * DINNER) { dst = g_k; cc0 = c0 - DINNER; }
    else                      { dst = g_v; cc0 = c0 - 2 * DINNER; }
    const int h = cc0 >> 6, d = cc0 & 63;
#pragma unroll
    for (int i = 0; i < 8; i++) {
        const int r  = row0 + ty * 8 + i;
        const int bb = r >> 10, n = r & 1023;
        float* p = dst + ((size_t)(bb * NUM_H + h) * NUM_N + n) * DHEAD + d;
        *reinterpret_cast<float4*>(p)     = make_float4(acc[i][0], acc[i][1], acc[i][2], acc[i][3]);
        *reinterpret_cast<float4*>(p + 4) = make_float4(acc[i][4], acc[i][5], acc[i][6], acc[i][7]);
    }
}

// ---------------------------------------------------------------------------
// Kernel 2: flash attention.  CTA = (h, i-block of 64 rows, b). 256 threads.
// Layouts chosen so every inner-loop access is conflict-free:
//   q_t[kk][row]  (pad 65)  - scalar broadcast reads
//   k_t[kk][j]    (pad 68)  - LDS.128, lane j-cols contiguous in row
//   v_s[j][d]     (pad 68)  - LDS.128, lane d-cols contiguous in row
//   p_s[row][j]   (pad 68)  - STS.128 writes, scalar broadcast reads
// ---------------------------------------------------------------------------
__global__ __launch_bounds__(256) void attn_kernel(
    const float* __restrict__ sim_bias,
    const int*   __restrict__ mask)
{
    extern __shared__ float sm[];
    float* q_t  = sm;                 // 64*65
    float* k_t  = q_t + 64 * 65;      // 64*68
    float* v_s  = k_t + 64 * 68;      // 64*68
    float* p_s  = v_s + 64 * 68;      // 64*68
    float* mk_s = p_s + 64 * 68;      // 64

    const int h  = blockIdx.x;
    const int i0 = blockIdx.y * 64;
    const int b  = blockIdx.z;
    const int tid = threadIdx.x;

    const float* qg = g_q + ((size_t)(b * NUM_H + h) * NUM_N + i0) * DHEAD;
    const float* kg = g_k + (size_t)(b * NUM_H + h) * NUM_N * DHEAD;
    const float* vg = g_v + (size_t)(b * NUM_H + h) * NUM_N * DHEAD;

    const int r  = tid >> 2;          // 0..63
    const int cb = (tid & 3) * 16;

    // load q tile (64x64) transposed into q_t[d][row]
#pragma unroll
    for (int u = 0; u < 4; u++) {
        float4 t = *reinterpret_cast<const float4*>(qg + (size_t)r * 64 + cb + u * 4);
        q_t[(cb + u * 4 + 0) * 65 + r] = t.x;
        q_t[(cb + u * 4 + 1) * 65 + r] = t.y;
        q_t[(cb + u * 4 + 2) * 65 + r] = t.z;
        q_t[(cb + u * 4 + 3) * 65 + r] = t.w;
    }

    const int lane = tid & 31;
    const int lr   = lane >> 3;       // 0..3
    const int ljg  = lane & 7;        // 0..7
    const int jc0  = ljg * 8;         // this lane's j (and d) column base
    const int r0   = (tid >> 5) * 8;  // warp row base
    const int rowA = r0 + lr;
    const int rowB = r0 + lr + 4;

    float m0 = NEG_BIG, m1 = NEG_BIG;
    float l0 = 0.f, l1 = 0.f;
    float o[2][8];
#pragma unroll
    for (int dd = 0; dd < 8; dd++) { o[0][dd] = 0.f; o[1][dd] = 0.f; }

    for (int jt = 0; jt < 16; jt++) {
        const int j0 = jt * 64;
        // cooperative load: k transposed (d-major), v row-major
#pragma unroll
        for (int u = 0; u < 4; u++) {
            float4 t = *reinterpret_cast<const float4*>(kg + (size_t)(j0 + r) * 64 + cb + u * 4);
            k_t[(cb + u * 4 + 0) * 68 + r] = t.x;
            k_t[(cb + u * 4 + 1) * 68 + r] = t.y;
            k_t[(cb + u * 4 + 2) * 68 + r] = t.z;
            k_t[(cb + u * 4 + 3) * 68 + r] = t.w;
            float4 tv = *reinterpret_cast<const float4*>(vg + (size_t)(j0 + r) * 64 + cb + u * 4);
            *reinterpret_cast<float4*>(&v_s[r * 68 + cb + u * 4]) = tv;
        }
        if (tid < 64) mk_s[tid] = mask[b * NUM_N + j0 + tid] ? 0.f : NEG_BIG;
        __syncthreads();

        // S = q @ k^T : lane -> 2 rows x 8 j-cols
        float s0[8], s1[8];
#pragma unroll
        for (int jj = 0; jj < 8; jj++) { s0[jj] = 0.f; s1[jj] = 0.f; }
#pragma unroll 8
        for (int kk = 0; kk < 64; kk++) {
            const float qa = q_t[kk * 65 + rowA];
            const float qb = q_t[kk * 65 + rowB];
            float4 k0v = *reinterpret_cast<const float4*>(&k_t[kk * 68 + jc0]);
            float4 k1v = *reinterpret_cast<const float4*>(&k_t[kk * 68 + jc0 + 4]);
            s0[0] += qa * k0v.x; s0[1] += qa * k0v.y; s0[2] += qa * k0v.z; s0[3] += qa * k0v.w;
            s0[4] += qa * k1v.x; s0[5] += qa * k1v.y; s0[6] += qa * k1v.z; s0[7] += qa * k1v.w;
            s1[0] += qb * k0v.x; s1[1] += qb * k0v.y; s1[2] += qb * k0v.z; s1[3] += qb * k0v.w;
            s1[4] += qb * k1v.x; s1[5] += qb * k1v.y; s1[6] += qb * k1v.z; s1[7] += qb * k1v.w;
        }

        // scale + bias + mask; bias layout [b, i, j, h]
        const float* bA = sim_bias + (((size_t)b * NUM_N + (i0 + rowA)) * NUM_N + (j0 + jc0)) * NUM_H + h;
        const float* bB = sim_bias + (((size_t)b * NUM_N + (i0 + rowB)) * NUM_N + (j0 + jc0)) * NUM_H + h;
        float mt0 = NEG_BIG, mt1 = NEG_BIG;
#pragma unroll
        for (int jj = 0; jj < 8; jj++) {
            const float mm = mk_s[jc0 + jj];
            s0[jj] = fmaf(s0[jj], QK_SCALE, __ldg(bA + jj * NUM_H) + mm);
            s1[jj] = fmaf(s1[jj], QK_SCALE, __ldg(bB + jj * NUM_H) + mm);
            mt0 = fmaxf(mt0, s0[jj]);
            mt1 = fmaxf(mt1, s1[jj]);
        }
#pragma unroll
        for (int off = 1; off < 8; off <<= 1) {
            mt0 = fmaxf(mt0, __shfl_xor_sync(0xffffffffu, mt0, off));
            mt1 = fmaxf(mt1, __shfl_xor_sync(0xffffffffu, mt1, off));
        }

        const float mn0 = fmaxf(m0, mt0), mn1 = fmaxf(m1, mt1);
        const float c0  = __expf(m0 - mn0), c1 = __expf(m1 - mn1);
        l0 *= c0; l1 *= c1;
#pragma unroll
        for (int dd = 0; dd < 8; dd++) { o[0][dd] *= c0; o[1][dd] *= c1; }

        float p0[8], p1[8];
        float rs0 = 0.f, rs1 = 0.f;
#pragma unroll
        for (int jj = 0; jj < 8; jj++) {
            p0[jj] = __expf(s0[jj] - mn0);
            p1[jj] = __expf(s1[jj] - mn1);
            rs0 += p0[jj]; rs1 += p1[jj];
        }
        *reinterpret_cast<float4*>(&p_s[rowA * 68 + jc0])     = make_float4(p0[0], p0[1], p0[2], p0[3]);
        *reinterpret_cast<float4*>(&p_s[rowA * 68 + jc0 + 4]) = make_float4(p0[4], p0[5], p0[6], p0[7]);
        *reinterpret_cast<float4*>(&p_s[rowB * 68 + jc0])     = make_float4(p1[0], p1[1], p1[2], p1[3]);
        *reinterpret_cast<float4*>(&p_s[rowB * 68 + jc0 + 4]) = make_float4(p1[4], p1[5], p1[6], p1[7]);
#pragma unroll
        for (int off = 1; off < 8; off <<= 1) {
            rs0 += __shfl_xor_sync(0xffffffffu, rs0, off);
            rs1 += __shfl_xor_sync(0xffffffffu, rs1, off);
        }
        l0 += rs0; l1 += rs1; m0 = mn0; m1 = mn1;
        __syncwarp();   // p_s rows are warp-private

        // O += P @ V : lane -> 2 rows x 8 d-cols (contiguous)
#pragma unroll 8
        for (int j = 0; j < 64; j++) {
            const float pa = p_s[rowA * 68 + j];
            const float pb = p_s[rowB * 68 + j];
            float4 v0 = *reinterpret_cast<const float4*>(&v_s[j * 68 + jc0]);
            float4 v1 = *reinterpret_cast<const float4*>(&v_s[j * 68 + jc0 + 4]);
            o[0][0] += pa * v0.x; o[0][1] += pa * v0.y; o[0][2] += pa * v0.z; o[0][3] += pa * v0.w;
            o[0][4] += pa * v1.x; o[0][5] += pa * v1.y; o[0][6] += pa * v1.z; o[0][7] += pa * v1.w;
            o[1][0] += pb * v0.x; o[1][1] += pb * v0.y; o[1][2] += pb * v0.z; o[1][3] += pb * v0.w;
            o[1][4] += pb * v1.x; o[1][5] += pb * v1.y; o[1][6] += pb * v1.z; o[1][7] += pb * v1.w;
        }
        __syncthreads();
    }

    const float inv0 = 1.f / l0, inv1 = 1.f / l1;
    float* oA = g_att + ((size_t)b * NUM_N + i0 + rowA) * DINNER + h * DHEAD + jc0;
    float* oB = g_att + ((size_t)b * NUM_N + i0 + rowB) * DINNER + h * DHEAD + jc0;
    *reinterpret_cast<float4*>(oA)     = make_float4(o[0][0]*inv0, o[0][1]*inv0, o[0][2]*inv0, o[0][3]*inv0);
    *reinterpret_cast<float4*>(oA + 4) = make_float4(o[0][4]*inv0, o[0][5]*inv0, o[0][6]*inv0, o[0][7]*inv0);
    *reinterpret_cast<float4*>(oB)     = make_float4(o[1][0]*inv1, o[1][1]*inv1, o[1][2]*inv1, o[1][3]*inv1);
    *reinterpret_cast<float4*>(oB + 4) = make_float4(o[1][4]*inv1, o[1][5]*inv1, o[1][6]*inv1, o[1][7]*inv1);
}

// ---------------------------------------------------------------------------
// Kernel 3: output projection.  out[8192 x 512] = att @ Wout + bout
// Same double-buffered 128x128 / 8x8 structure as kernel 1.
// ---------------------------------------------------------------------------
__global__ __launch_bounds__(256) void out_gemm_kernel(
    const float* __restrict__ Wout,
    const float* __restrict__ bout,
    float* __restrict__ out)
{
    __shared__ float As[2][16][132];
    __shared__ float Bs[2][16][132];

    const int tid  = threadIdx.x;
    const int tx   = tid & 15, ty = tid >> 4;
    const int row0 = blockIdx.y * 128;
    const int col0 = blockIdx.x * 128;

    const int ar = tid >> 1, ac = (tid & 1) * 8;
    const int br = tid >> 4, bc = (tid & 15) * 8;

    const float* ag = g_att + (size_t)(row0 + ar) * DINNER + ac;
    const float* bg = Wout + (size_t)br * DOUT + col0 + bc;

    float acc[8][8];
#pragma unroll
    for (int i = 0; i < 8; i++)
#pragma unroll
        for (int j = 0; j < 8; j++) acc[i][j] = 0.f;

    float4 ra0 = *reinterpret_cast<const float4*>(ag);
    float4 ra1 = *reinterpret_cast<const float4*>(ag + 4);
    float4 rb0 = *reinterpret_cast<const float4*>(bg);
    float4 rb1 = *reinterpret_cast<const float4*>(bg + 4);

    As[0][ac + 0][ar] = ra0.x; As[0][ac + 1][ar] = ra0.y;
    As[0][ac + 2][ar] = ra0.z; As[0][ac + 3][ar] = ra0.w;
    As[0][ac + 4][ar] = ra1.x; As[0][ac + 5][ar] = ra1.y;
    As[0][ac + 6][ar] = ra1.z; As[0][ac + 7][ar] = ra1.w;
    *reinterpret_cast<float4*>(&Bs[0][br][bc])     = rb0;
    *reinterpret_cast<float4*>(&Bs[0][br][bc + 4]) = rb1;
    __syncthreads();

    for (int k0 = 0; k0 < DINNER; k0 += 16) {
        const int buf = (k0 >> 4) & 1;
        const bool more = (k0 + 16 < DINNER);
        if (more) {
            ra0 = *reinterpret_cast<const float4*>(ag + k0 + 16);
            ra1 = *reinterpret_cast<const float4*>(ag + k0 + 20);
            rb0 = *reinterpret_cast<const float4*>(bg + (size_t)(k0 + 16) * DOUT);
            rb1 = *reinterpret_cast<const float4*>(bg + (size_t)(k0 + 16) * DOUT + 4);
        }

#pragma unroll
        for (int kk = 0; kk < 16; kk++) {
            float a[8], b[8];
            float4 t;
            t = *reinterpret_cast<const float4*>(&As[buf][kk][ty * 8]);     a[0]=t.x; a[1]=t.y; a[2]=t.z; a[3]=t.w;
            t = *reinterpret_cast<const float4*>(&As[buf][kk][ty * 8 + 4]); a[4]=t.x; a[5]=t.y; a[6]=t.z; a[7]=t.w;
            t = *reinterpret_cast<const float4*>(&Bs[buf][kk][tx * 8]);     b[0]=t.x; b[1]=t.y; b[2]=t.z; b[3]=t.w;
            t = *reinterpret_cast<const float4*>(&Bs[buf][kk][tx * 8 + 4]); b[4]=t.x; b[5]=t.y; b[6]=t.z; b[7]=t.w;
#pragma unroll
            for (int i = 0; i < 8; i++)
#pragma unroll
                for (int j = 0; j < 8; j++) acc[i][j] += a[i] * b[j];
        }

        if (more) {
            const int nb = buf ^ 1;
            As[nb][ac + 0][ar] = ra0.x; As[nb][ac + 1][ar] = ra0.y;
            As[nb][ac + 2][ar] = ra0.z; As[nb][ac + 3][ar] = ra0.w;
            As[nb][ac + 4][ar] = ra1.x; As[nb][ac + 5][ar] = ra1.y;
            As[nb][ac + 6][ar] = ra1.z; As[nb][ac + 7][ar] = ra1.w;
            *reinterpret_cast<float4*>(&Bs[nb][br][bc])     = rb0;
            *reinterpret_cast<float4*>(&Bs[nb][br][bc + 4]) = rb1;
            __syncthreads();
        }
    }

    const int c0 = col0 + tx * 8;
    float4 bv0 = *reinterpret_cast<const float4*>(bout + c0);
    float4 bv1 = *reinterpret_cast<const float4*>(bout + c0 + 4);
#pragma unroll
    for (int i = 0; i < 8; i++) {
        const int rr = row0 + ty * 8 + i;
        *reinterpret_cast<float4*>(out + (size_t)rr * DOUT + c0) =
            make_float4(acc[i][0] + bv0.x, acc[i][1] + bv0.y, acc[i][2] + bv0.z, acc[i][3] + bv0.w);
        *reinterpret_cast<float4*>(out + (size_t)rr * DOUT + c0 + 4) =
            make_float4(acc[i][4] + bv1.x, acc[i][5] + bv1.y, acc[i][6] + bv1.z, acc[i][7] + bv1.w);
    }
}

// ---------------------------------------------------------------------------
extern "C" void kernel_launch(void* const* d_in, const int* in_sizes, int n_in,
                              void* d_out, int out_size)
{
    const float* x    = (const float*)d_in[0];
    const int*   mask = (const int*)  d_in[1];
    const float* sb   = (const float*)d_in[2];
    const float* Wq   = (const float*)d_in[3];
    const float* Wkv  = (const float*)d_in[4];
    const float* Wout = (const float*)d_in[5];
    const float* bout = (const float*)d_in[6];
    float* out = (float*)d_out;

    // 1) QKV projection: 8192 x 1536 (12 x 64 tiles of 128x128)
    qkv_gemm_kernel<<<dim3(12, 64), 256>>>(x, Wq, Wkv);

    // 2) flash attention; h fastest in grid for bias L2 sector reuse across heads
    const int smem = (64 * 65 + 64 * 68 * 3 + 64) * (int)sizeof(float);  // 69,120 B
    cudaFuncSetAttribute(attn_kernel, cudaFuncAttributeMaxDynamicSharedMemorySize, smem);
    attn_kernel<<<dim3(NUM_H, NUM_N / 64, NUM_B), 256, smem>>>(sb, mask);

    // 3) output projection: 8192 x 512 (4 x 64 tiles of 128x128)
    out_gemm_kernel<<<dim3(4, 64), 256>>>(Wout, bout, out);
}

// round 5
// speedup vs baseline: 4.3061x; 2.4970x over previous
#include <cuda_runtime.h>
#include <cuda_bf16.h>
#include <cstdint>
#include <cstddef>

#define NUM_B   8
#define NUM_N   1024
#define NUM_H   8
#define DHEAD   64
#define DIN     512
#define DINNER  512
#define DOUT    512
#define QK_SCALE 0.125f

// Scratch (allocation-free: device globals)
__device__ float g_q[NUM_B * NUM_H * NUM_N * DHEAD];
__device__ float g_k[NUM_B * NUM_H * NUM_N * DHEAD];
__device__ float g_v[NUM_B * NUM_H * NUM_N * DHEAD];
__device__ float g_att[NUM_B * NUM_N * DINNER];
__device__ float g_biasT[(size_t)NUM_B * NUM_H * NUM_N * NUM_N];   // [b][h][i][j]

// ===========================================================================
// helpers
// ===========================================================================
__device__ __forceinline__ uint32_t smem_to_u32(const void* p) {
    uint32_t a;
    asm("{ .reg .u64 t; cvta.to.shared.u64 t, %1; cvt.u32.u64 %0, t; }" : "=r"(a) : "l"(p));
    return a;
}
__device__ __forceinline__ void ldmx4(uint32_t* r, uint32_t addr) {
    asm volatile("ldmatrix.sync.aligned.m8n8.x4.shared.b16 {%0,%1,%2,%3}, [%4];"
        : "=r"(r[0]), "=r"(r[1]), "=r"(r[2]), "=r"(r[3]) : "r"(addr));
}
__device__ __forceinline__ void ldmx2(uint32_t* r, uint32_t addr) {
    asm volatile("ldmatrix.sync.aligned.m8n8.x2.shared.b16 {%0,%1}, [%2];"
        : "=r"(r[0]), "=r"(r[1]) : "r"(addr));
}
__device__ __forceinline__ void ldmx2t(uint32_t* r, uint32_t addr) {
    asm volatile("ldmatrix.sync.aligned.m8n8.x2.trans.shared.b16 {%0,%1}, [%2];"
        : "=r"(r[0]), "=r"(r[1]) : "r"(addr));
}
__device__ __forceinline__ void mma16816(float* c, const uint32_t* a, const uint32_t* b) {
    asm volatile("mma.sync.aligned.m16n8k16.row.col.f32.bf16.bf16.f32 "
        "{%0,%1,%2,%3}, {%4,%5,%6,%7}, {%8,%9}, {%0,%1,%2,%3};"
        : "+f"(c[0]), "+f"(c[1]), "+f"(c[2]), "+f"(c[3])
        : "r"(a[0]), "r"(a[1]), "r"(a[2]), "r"(a[3]), "r"(b[0]), "r"(b[1]));
}
__device__ __forceinline__ void split_bf16(float x, __nv_bfloat16& hi, __nv_bfloat16& lo) {
    hi = __float2bfloat16_rn(x);
    lo = __float2bfloat16_rn(x - __bfloat162float(hi));
}
__device__ __forceinline__ uint32_t packbf2(float x, float y) {
    __nv_bfloat162 t = __floats2bfloat162_rn(x, y);   // x -> low half
    return *reinterpret_cast<uint32_t*>(&t);
}

// ===========================================================================
// Kernel 1: fused QKV projection (SIMT fp32)
// ===========================================================================
__global__ __launch_bounds__(256) void qkv_gemm_kernel(
    const float* __restrict__ x, const float* __restrict__ Wq, const float* __restrict__ Wkv)
{
    __shared__ float As[2][16][132];
    __shared__ float Bs[2][16][132];
    const int tid = threadIdx.x;
    const int tx = tid & 15, ty = tid >> 4;
    const int row0 = blockIdx.y * 128, col0 = blockIdx.x * 128;
    const float* W; int wld, wc0;
    if (col0 < DINNER) { W = Wq;  wld = DINNER;     wc0 = col0; }
    else               { W = Wkv; wld = 2 * DINNER; wc0 = col0 - DINNER; }
    const int ar = tid >> 1, ac = (tid & 1) * 8;
    const int br = tid >> 4, bc = (tid & 15) * 8;
    const float* ag = x + (size_t)(row0 + ar) * DIN + ac;
    const float* bg = W + (size_t)br * wld + wc0 + bc;
    float acc[8][8];
#pragma unroll
    for (int i = 0; i < 8; i++)
#pragma unroll
        for (int j = 0; j < 8; j++) acc[i][j] = 0.f;
    float4 ra0 = *reinterpret_cast<const float4*>(ag);
    float4 ra1 = *reinterpret_cast<const float4*>(ag + 4);
    float4 rb0 = *reinterpret_cast<const float4*>(bg);
    float4 rb1 = *reinterpret_cast<const float4*>(bg + 4);
    As[0][ac+0][ar]=ra0.x; As[0][ac+1][ar]=ra0.y; As[0][ac+2][ar]=ra0.z; As[0][ac+3][ar]=ra0.w;
    As[0][ac+4][ar]=ra1.x; As[0][ac+5][ar]=ra1.y; As[0][ac+6][ar]=ra1.z; As[0][ac+7][ar]=ra1.w;
    *reinterpret_cast<float4*>(&Bs[0][br][bc])   = rb0;
    *reinterpret_cast<float4*>(&Bs[0][br][bc+4]) = rb1;
    __syncthreads();
    for (int k0 = 0; k0 < DIN; k0 += 16) {
        const int buf = (k0 >> 4) & 1;
        const bool more = (k0 + 16 < DIN);
        if (more) {
            ra0 = *reinterpret_cast<const float4*>(ag + k0 + 16);
            ra1 = *reinterpret_cast<const float4*>(ag + k0 + 20);
            rb0 = *reinterpret_cast<const float4*>(bg + (size_t)(k0 + 16) * wld);
            rb1 = *reinterpret_cast<const float4*>(bg + (size_t)(k0 + 16) * wld + 4);
        }
#pragma unroll
        for (int kk = 0; kk < 16; kk++) {
            float a[8], b[8]; float4 t;
            t = *reinterpret_cast<const float4*>(&As[buf][kk][ty*8]);   a[0]=t.x;a[1]=t.y;a[2]=t.z;a[3]=t.w;
            t = *reinterpret_cast<const float4*>(&As[buf][kk][ty*8+4]); a[4]=t.x;a[5]=t.y;a[6]=t.z;a[7]=t.w;
            t = *reinterpret_cast<const float4*>(&Bs[buf][kk][tx*8]);   b[0]=t.x;b[1]=t.y;b[2]=t.z;b[3]=t.w;
            t = *reinterpret_cast<const float4*>(&Bs[buf][kk][tx*8+4]); b[4]=t.x;b[5]=t.y;b[6]=t.z;b[7]=t.w;
#pragma unroll
            for (int i = 0; i < 8; i++)
#pragma unroll
                for (int j = 0; j < 8; j++) acc[i][j] += a[i] * b[j];
        }
        if (more) {
            const int nb = buf ^ 1;
            As[nb][ac+0][ar]=ra0.x; As[nb][ac+1][ar]=ra0.y; As[nb][ac+2][ar]=ra0.z; As[nb][ac+3][ar]=ra0.w;
            As[nb][ac+4][ar]=ra1.x; As[nb][ac+5][ar]=ra1.y; As[nb][ac+6][ar]=ra1.z; As[nb][ac+7][ar]=ra1.w;
            *reinterpret_cast<float4*>(&Bs[nb][br][bc])   = rb0;
            *reinterpret_cast<float4*>(&Bs[nb][br][bc+4]) = rb1;
            __syncthreads();
        }
    }
    const int c0 = col0 + tx * 8;
    float* dst; int cc0;
    if (c0 < DINNER)          { dst = g_q; cc0 = c0; }
    else if (c0 < 2 * DINNER) { dst = g_k; cc0 = c0 - DINNER; }
    else                      { dst = g_v; cc0 = c0 - 2 * DINNER; }
    const int h = cc0 >> 6, d = cc0 & 63;
#pragma unroll
    for (int i = 0; i < 8; i++) {
        const int r = row0 + ty * 8 + i;
        const int bb = r >> 10, n = r & 1023;
        float* p = dst + ((size_t)(bb * NUM_H + h) * NUM_N + n) * DHEAD + d;
        *reinterpret_cast<float4*>(p)     = make_float4(acc[i][0], acc[i][1], acc[i][2], acc[i][3]);
        *reinterpret_cast<float4*>(p + 4) = make_float4(acc[i][4], acc[i][5], acc[i][6], acc[i][7]);
    }
}

// ===========================================================================
// Kernel 1b: bias transpose  [b][i][j][h] -> [b][h][i][j]
// ===========================================================================
__global__ __launch_bounds__(256) void bias_transpose_kernel(const float* __restrict__ in)
{
    __shared__ float sm[8 * 32 * 33];
    const int tid = threadIdx.x;
    const int j0 = blockIdx.x * 32;
    const int i0 = blockIdx.y * 32;
    const int b  = blockIdx.z;
#pragma unroll
    for (int k = 0; k < 8; k++) {
        const int idx = tid + k * 256;
        const int ii = idx >> 6;
        const int f  = idx & 63;
        const float4 v = *reinterpret_cast<const float4*>(
            in + (((size_t)b * NUM_N + i0 + ii) * NUM_N + j0) * NUM_H + f * 4);
        const int jj = f >> 1;
        const int h0 = (f & 1) * 4;
        sm[(h0 + 0) * (32 * 33) + ii * 33 + jj] = v.x;
        sm[(h0 + 1) * (32 * 33) + ii * 33 + jj] = v.y;
        sm[(h0 + 2) * (32 * 33) + ii * 33 + jj] = v.z;
        sm[(h0 + 3) * (32 * 33) + ii * 33 + jj] = v.w;
    }
    __syncthreads();
#pragma unroll
    for (int k = 0; k < 8; k++) {
        const int idx = tid + k * 256;
        const int rowid = idx >> 3;
        const int h  = rowid >> 5;
        const int ii = rowid & 31;
        const int jj0 = (idx & 7) * 4;
        float4 v;
        v.x = sm[h * (32 * 33) + ii * 33 + jj0 + 0];
        v.y = sm[h * (32 * 33) + ii * 33 + jj0 + 1];
        v.z = sm[h * (32 * 33) + ii * 33 + jj0 + 2];
        v.w = sm[h * (32 * 33) + ii * 33 + jj0 + 3];
        *reinterpret_cast<float4*>(
            g_biasT + (((size_t)(b * NUM_H + h) * NUM_N) + i0 + ii) * NUM_N + j0 + jj0) = v;
    }
}

// ===========================================================================
// Kernel 2: warp-MMA flash attention (bf16 hi/lo 3-term split, fp32 accum).
// CTA = (i-tile 128, h, b), 128 threads (4 warps, warp -> 32 q-rows).
// No online max (scores bounded); masked keys -> p = 0.
// ===========================================================================
#define AT_QHI  0
#define AT_QLO  18432
#define AT_KHI  36864
#define AT_KLO  46080
#define AT_VHI  55296
#define AT_VLO  64512
#define AT_MK   73728
#define AT_TOTAL 73984
#define PAD 72

__global__ __launch_bounds__(128) void attn_mma_kernel(const int* __restrict__ mask)
{
    extern __shared__ char smem[];
    const uint32_t sb = smem_to_u32(smem);
    const int tid  = threadIdx.x;
    const int lane = tid & 31;
    const int w    = tid >> 5;
    const int i0   = blockIdx.x * 128;
    const int h    = blockIdx.y;
    const int bz   = blockIdx.z;

    // ---- stage Q (128x64) split hi/lo, row = tid, pad 72 ----
    {
        const float* qg = g_q + ((size_t)(bz * NUM_H + h) * NUM_N + i0 + tid) * DHEAD;
        float qv[64];
#pragma unroll
        for (int u = 0; u < 16; u++) {
            float4 t = *reinterpret_cast<const float4*>(qg + u * 4);
            qv[u*4+0] = t.x; qv[u*4+1] = t.y; qv[u*4+2] = t.z; qv[u*4+3] = t.w;
        }
#pragma unroll
        for (int cp = 0; cp < 32; cp++) {
            __nv_bfloat16 h0, l0, h1, l1;
            split_bf16(qv[2*cp],   h0, l0);
            split_bf16(qv[2*cp+1], h1, l1);
            const uint32_t off = (uint32_t)(tid * PAD + 2 * cp) * 2;
            *reinterpret_cast<__nv_bfloat162*>(smem + AT_QHI + off) = __halves2bfloat162(h0, h1);
            *reinterpret_cast<__nv_bfloat162*>(smem + AT_QLO + off) = __halves2bfloat162(l0, l1);
        }
    }

    const int g  = lane >> 2;     // 0..7
    const int tg = lane & 3;      // 0..3
    // ldmatrix lane addressing
    const int arow = (lane & 15);
    const int acol = (lane >> 4) * 8;
    const int brow = (lane & 7);
    const int bcol = ((lane >> 3) & 1) * 8;

    float O[2][8][4];
#pragma unroll
    for (int m = 0; m < 2; m++)
#pragma unroll
        for (int n = 0; n < 8; n++)
#pragma unroll
            for (int c = 0; c < 4; c++) O[m][n][c] = 0.f;
    float lsum[2][2] = {{0.f, 0.f}, {0.f, 0.f}};

    const int krow = tid >> 1;
    const int kc0  = (tid & 1) * 32;
    float* mk = reinterpret_cast<float*>(smem + AT_MK);

    for (int jt = 0; jt < 16; jt++) {
        const int j0 = jt * 64;
        __syncthreads();   // previous iteration's K/V reads done (covers Q stage at jt=0)

        // ---- stage K, V (64x64) split hi/lo ----
        {
            const float* kgp = g_k + ((size_t)(bz * NUM_H + h) * NUM_N + j0 + krow) * DHEAD + kc0;
            const float* vgp = g_v + ((size_t)(bz * NUM_H + h) * NUM_N + j0 + krow) * DHEAD + kc0;
            float kv[32], vv[32];
#pragma unroll
            for (int u = 0; u < 8; u++) {
                float4 t = *reinterpret_cast<const float4*>(kgp + u * 4);
                kv[u*4+0]=t.x; kv[u*4+1]=t.y; kv[u*4+2]=t.z; kv[u*4+3]=t.w;
                float4 s = *reinterpret_cast<const float4*>(vgp + u * 4);
                vv[u*4+0]=s.x; vv[u*4+1]=s.y; vv[u*4+2]=s.z; vv[u*4+3]=s.w;
            }
#pragma unroll
            for (int cp = 0; cp < 16; cp++) {
                const uint32_t off = (uint32_t)(krow * PAD + kc0 + 2 * cp) * 2;
                __nv_bfloat16 h0, l0, h1, l1;
                split_bf16(kv[2*cp],   h0, l0);
                split_bf16(kv[2*cp+1], h1, l1);
                *reinterpret_cast<__nv_bfloat162*>(smem + AT_KHI + off) = __halves2bfloat162(h0, h1);
                *reinterpret_cast<__nv_bfloat162*>(smem + AT_KLO + off) = __halves2bfloat162(l0, l1);
                split_bf16(vv[2*cp],   h0, l0);
                split_bf16(vv[2*cp+1], h1, l1);
                *reinterpret_cast<__nv_bfloat162*>(smem + AT_VHI + off) = __halves2bfloat162(h0, h1);
                *reinterpret_cast<__nv_bfloat162*>(smem + AT_VLO + off) = __halves2bfloat162(l0, l1);
            }
        }
        if (tid < 64) mk[tid] = mask[bz * NUM_N + j0 + tid] ? 1.f : 0.f;
        __syncthreads();

        // ---- S = Q K^T : 3 split terms ----
        float S[2][8][4];
#pragma unroll
        for (int m = 0; m < 2; m++)
#pragma unroll
            for (int n = 0; n < 8; n++)
#pragma unroll
                for (int c = 0; c < 4; c++) S[m][n][c] = 0.f;

#pragma unroll
        for (int ks = 0; ks < 4; ks++) {
            uint32_t ah[2][4], al[2][4];
#pragma unroll
            for (int m = 0; m < 2; m++) {
                const uint32_t aoff = sb + AT_QHI +
                    (uint32_t)((32 * w + 16 * m + arow) * PAD + ks * 16 + acol) * 2;
                ldmx4(ah[m], aoff);
                ldmx4(al[m], aoff + (AT_QLO - AT_QHI));
            }
#pragma unroll
            for (int n = 0; n < 8; n++) {
                uint32_t bh[2], bl[2];
                const uint32_t boff = sb + AT_KHI +
                    (uint32_t)((n * 8 + brow) * PAD + ks * 16 + bcol) * 2;
                ldmx2(bh, boff);
                ldmx2(bl, boff + (AT_KLO - AT_KHI));
#pragma unroll
                for (int m = 0; m < 2; m++) {
                    mma16816(S[m][n], ah[m], bh);
                    mma16816(S[m][n], al[m], bh);
                    mma16816(S[m][n], ah[m], bl);
                }
            }
        }

        // ---- softmax -> P fragments (registers only) ----
        uint32_t ph[2][4][4], pl[2][4][4];
#pragma unroll
        for (int m = 0; m < 2; m++) {
            const int r1 = i0 + 32 * w + 16 * m + g;
            const float* bp1 = g_biasT + ((size_t)(bz * NUM_H + h) * NUM_N + r1) * NUM_N + j0 + tg * 2;
            const float* bp2 = bp1 + 8 * NUM_N;
#pragma unroll
            for (int n = 0; n < 8; n++) {
                const float2 bb1 = *reinterpret_cast<const float2*>(bp1 + n * 8);
                const float2 bb2 = *reinterpret_cast<const float2*>(bp2 + n * 8);
                const float2 mm  = *reinterpret_cast<const float2*>(mk + n * 8 + tg * 2);
                const float p0 = mm.x * __expf(fmaf(S[m][n][0], QK_SCALE, bb1.x));
                const float p1 = mm.y * __expf(fmaf(S[m][n][1], QK_SCALE, bb1.y));
                const float p2 = mm.x * __expf(fmaf(S[m][n][2], QK_SCALE, bb2.x));
                const float p3 = mm.y * __expf(fmaf(S[m][n][3], QK_SCALE, bb2.y));
                lsum[m][0] += p0 + p1;
                lsum[m][1] += p2 + p3;
                // pack into A-fragment layout for PV: kc = n/2, regs (n&1)*2, +1
                const int kc = n >> 1;
                const int rb = (n & 1) * 2;
                __nv_bfloat16 hx, lx, hy, ly;
                split_bf16(p0, hx, lx); split_bf16(p1, hy, ly);
                ph[m][kc][rb]   = packbf2(__bfloat162float(hx), __bfloat162float(hy));
                pl[m][kc][rb]   = packbf2(__bfloat162float(lx), __bfloat162float(ly));
                split_bf16(p2, hx, lx); split_bf16(p3, hy, ly);
                ph[m][kc][rb+1] = packbf2(__bfloat162float(hx), __bfloat162float(hy));
                pl[m][kc][rb+1] = packbf2(__bfloat162float(lx), __bfloat162float(ly));
            }
        }

        // ---- O += P V : 3 split terms ----
#pragma unroll
        for (int kc = 0; kc < 4; kc++) {
#pragma unroll
            for (int n = 0; n < 8; n++) {
                uint32_t vh[2], vl[2];
                const uint32_t voff = sb + AT_VHI +
                    (uint32_t)((kc * 16 + (lane & 15)) * PAD + n * 8) * 2;
                ldmx2t(vh, voff);
                ldmx2t(vl, voff + (AT_VLO - AT_VHI));
#pragma unroll
                for (int m = 0; m < 2; m++) {
                    mma16816(O[m][n], ph[m][kc], vh);
                    mma16816(O[m][n], ph[m][kc], vl);
                    mma16816(O[m][n], pl[m][kc], vh);
                }
            }
        }
    }

    // ---- epilogue: reduce lsum across the 4-thread group, write O/l ----
#pragma unroll
    for (int m = 0; m < 2; m++)
#pragma unroll
        for (int r = 0; r < 2; r++) {
            lsum[m][r] += __shfl_xor_sync(0xffffffffu, lsum[m][r], 1);
            lsum[m][r] += __shfl_xor_sync(0xffffffffu, lsum[m][r], 2);
        }
#pragma unroll
    for (int m = 0; m < 2; m++) {
        const int r1 = i0 + 32 * w + 16 * m + g;
        const float inv1 = 1.f / lsum[m][0];
        const float inv2 = 1.f / lsum[m][1];
        float* o1 = g_att + ((size_t)bz * NUM_N + r1) * DINNER + h * DHEAD + tg * 2;
        float* o2 = o1 + 8 * DINNER;
#pragma unroll
        for (int n = 0; n < 8; n++) {
            *reinterpret_cast<float2*>(o1 + n * 8) = make_float2(O[m][n][0] * inv1, O[m][n][1] * inv1);
            *reinterpret_cast<float2*>(o2 + n * 8) = make_float2(O[m][n][2] * inv2, O[m][n][3] * inv2);
        }
    }
}

// ===========================================================================
// Kernel 3: output projection (SIMT fp32)
// ===========================================================================
__global__ __launch_bounds__(256) void out_gemm_kernel(
    const float* __restrict__ Wout, const float* __restrict__ bout, float* __restrict__ out)
{
    __shared__ float As[2][16][132];
    __shared__ float Bs[2][16][132];
    const int tid = threadIdx.x;
    const int tx = tid & 15, ty = tid >> 4;
    const int row0 = blockIdx.y * 128, col0 = blockIdx.x * 128;
    const int ar = tid >> 1, ac = (tid & 1) * 8;
    const int br = tid >> 4, bc = (tid & 15) * 8;
    const float* ag = g_att + (size_t)(row0 + ar) * DINNER + ac;
    const float* bg = Wout + (size_t)br * DOUT + col0 + bc;
    float acc[8][8];
#pragma unroll
    for (int i = 0; i < 8; i++)
#pragma unroll
        for (int j = 0; j < 8; j++) acc[i][j] = 0.f;
    float4 ra0 = *reinterpret_cast<const float4*>(ag);
    float4 ra1 = *reinterpret_cast<const float4*>(ag + 4);
    float4 rb0 = *reinterpret_cast<const float4*>(bg);
    float4 rb1 = *reinterpret_cast<const float4*>(bg + 4);
    As[0][ac+0][ar]=ra0.x; As[0][ac+1][ar]=ra0.y; As[0][ac+2][ar]=ra0.z; As[0][ac+3][ar]=ra0.w;
    As[0][ac+4][ar]=ra1.x; As[0][ac+5][ar]=ra1.y; As[0][ac+6][ar]=ra1.z; As[0][ac+7][ar]=ra1.w;
    *reinterpret_cast<float4*>(&Bs[0][br][bc])   = rb0;
    *reinterpret_cast<float4*>(&Bs[0][br][bc+4]) = rb1;
    __syncthreads();
    for (int k0 = 0; k0 < DINNER; k0 += 16) {
        const int buf = (k0 >> 4) & 1;
        const bool more = (k0 + 16 < DINNER);
        if (more) {
            ra0 = *reinterpret_cast<const float4*>(ag + k0 + 16);
            ra1 = *reinterpret_cast<const float4*>(ag + k0 + 20);
            rb0 = *reinterpret_cast<const float4*>(bg + (size_t)(k0 + 16) * DOUT);
            rb1 = *reinterpret_cast<const float4*>(bg + (size_t)(k0 + 16) * DOUT + 4);
        }
#pragma unroll
        for (int kk = 0; kk < 16; kk++) {
            float a[8], b[8]; float4 t;
            t = *reinterpret_cast<const float4*>(&As[buf][kk][ty*8]);   a[0]=t.x;a[1]=t.y;a[2]=t.z;a[3]=t.w;
            t = *reinterpret_cast<const float4*>(&As[buf][kk][ty*8+4]); a[4]=t.x;a[5]=t.y;a[6]=t.z;a[7]=t.w;
            t = *reinterpret_cast<const float4*>(&Bs[buf][kk][tx*8]);   b[0]=t.x;b[1]=t.y;b[2]=t.z;b[3]=t.w;
            t = *reinterpret_cast<const float4*>(&Bs[buf][kk][tx*8+4]); b[4]=t.x;b[5]=t.y;b[6]=t.z;b[7]=t.w;
#pragma unroll
            for (int i = 0; i < 8; i++)
#pragma unroll
                for (int j = 0; j < 8; j++) acc[i][j] += a[i] * b[j];
        }
        if (more) {
            const int nb = buf ^ 1;
            As[nb][ac+0][ar]=ra0.x; As[nb][ac+1][ar]=ra0.y; As[nb][ac+2][ar]=ra0.z; As[nb][ac+3][ar]=ra0.w;
            As[nb][ac+4][ar]=ra1.x; As[nb][ac+5][ar]=ra1.y; As[nb][ac+6][ar]=ra1.z; As[nb][ac+7][ar]=ra1.w;
            *reinterpret_cast<float4*>(&Bs[nb][br][bc])   = rb0;
            *reinterpret_cast<float4*>(&Bs[nb][br][bc+4]) = rb1;
            __syncthreads();
        }
    }
    const int c0 = col0 + tx * 8;
    float4 bv0 = *reinterpret_cast<const float4*>(bout + c0);
    float4 bv1 = *reinterpret_cast<const float4*>(bout + c0 + 4);
#pragma unroll
    for (int i = 0; i < 8; i++) {
        const int rr = row0 + ty * 8 + i;
        *reinterpret_cast<float4*>(out + (size_t)rr * DOUT + c0) =
            make_float4(acc[i][0] + bv0.x, acc[i][1] + bv0.y, acc[i][2] + bv0.z, acc[i][3] + bv0.w);
        *reinterpret_cast<float4*>(out + (size_t)rr * DOUT + c0 + 4) =
            make_float4(acc[i][4] + bv1.x, acc[i][5] + bv1.y, acc[i][6] + bv1.z, acc[i][7] + bv1.w);
    }
}

// ---------------------------------------------------------------------------
extern "C" void kernel_launch(void* const* d_in, const int* in_sizes, int n_in,
                              void* d_out, int out_size)
{
    const float* x    = (const float*)d_in[0];
    const int*   mask = (const int*)  d_in[1];
    const float* sb   = (const float*)d_in[2];
    const float* Wq   = (const float*)d_in[3];
    const float* Wkv  = (const float*)d_in[4];
    const float* Wout = (const float*)d_in[5];
    const float* bout = (const float*)d_in[6];
    float* out = (float*)d_out;

    // 1) QKV projection
    qkv_gemm_kernel<<<dim3(12, 64), 256>>>(x, Wq, Wkv);

    // 1b) bias transpose [b,i,j,h] -> [b,h,i,j]
    bias_transpose_kernel<<<dim3(32, 32, NUM_B), 256>>>(sb);

    // 2) warp-MMA flash attention
    cudaFuncSetAttribute(attn_mma_kernel, cudaFuncAttributeMaxDynamicSharedMemorySize, AT_TOTAL);
    attn_mma_kernel<<<dim3(NUM_N / 128, NUM_H, NUM_B), 128, AT_TOTAL>>>(mask);

    // 3) output projection
    out_gemm_kernel<<<dim3(4, 64), 256>>>(Wout, bout, out);
}

// round 8
// speedup vs baseline: 4.6768x; 1.0861x over previous
#include <cuda_runtime.h>
#include <cuda_bf16.h>
#include <cstdint>
#include <cstddef>

#define NUM_B   8
#define NUM_N   1024
#define NUM_H   8
#define DHEAD   64
#define DIN     512
#define DINNER  512
#define DOUT    512
#define QK_SCALE 0.125f

// Scratch (allocation-free: device globals) — same set as passing R5
__device__ float g_q[NUM_B * NUM_H * NUM_N * DHEAD];
__device__ float g_k[NUM_B * NUM_H * NUM_N * DHEAD];
__device__ float g_v[NUM_B * NUM_H * NUM_N * DHEAD];
__device__ float g_att[NUM_B * NUM_N * DINNER];
__device__ float g_biasT[(size_t)NUM_B * NUM_H * NUM_N * NUM_N];   // [b][h][i][j]

// ===========================================================================
// helpers
// ===========================================================================
__device__ __forceinline__ uint32_t smem_to_u32(const void* p) {
    uint32_t a;
    asm("{ .reg .u64 t; cvta.to.shared.u64 t, %1; cvt.u32.u64 %0, t; }" : "=r"(a) : "l"(p));
    return a;
}
__device__ __forceinline__ void ldmx4(uint32_t* r, uint32_t addr) {
    asm volatile("ldmatrix.sync.aligned.m8n8.x4.shared.b16 {%0,%1,%2,%3}, [%4];"
        : "=r"(r[0]), "=r"(r[1]), "=r"(r[2]), "=r"(r[3]) : "r"(addr));
}
__device__ __forceinline__ void ldmx2(uint32_t* r, uint32_t addr) {
    asm volatile("ldmatrix.sync.aligned.m8n8.x2.shared.b16 {%0,%1}, [%2];"
        : "=r"(r[0]), "=r"(r[1]) : "r"(addr));
}
__device__ __forceinline__ void ldmx2t(uint32_t* r, uint32_t addr) {
    asm volatile("ldmatrix.sync.aligned.m8n8.x2.trans.shared.b16 {%0,%1}, [%2];"
        : "=r"(r[0]), "=r"(r[1]) : "r"(addr));
}
__device__ __forceinline__ void mma16816(float* c, const uint32_t* a, const uint32_t* b) {
    asm volatile("mma.sync.aligned.m16n8k16.row.col.f32.bf16.bf16.f32 "
        "{%0,%1,%2,%3}, {%4,%5,%6,%7}, {%8,%9}, {%0,%1,%2,%3};"
        : "+f"(c[0]), "+f"(c[1]), "+f"(c[2]), "+f"(c[3])
        : "r"(a[0]), "r"(a[1]), "r"(a[2]), "r"(a[3]), "r"(b[0]), "r"(b[1]));
}
__device__ __forceinline__ void split_bf16(float x, __nv_bfloat16& hi, __nv_bfloat16& lo) {
    hi = __float2bfloat16_rn(x);
    lo = __float2bfloat16_rn(x - __bfloat162float(hi));
}
__device__ __forceinline__ uint32_t packbf2(float x, float y) {
    __nv_bfloat162 t = __floats2bfloat162_rn(x, y);   // x -> low half
    return *reinterpret_cast<uint32_t*>(&t);
}
__device__ __forceinline__ void split2_pack(float a, float b, uint32_t& hp, uint32_t& lp) {
    __nv_bfloat16 h0, l0, h1, l1;
    split_bf16(a, h0, l0); split_bf16(b, h1, l1);
    __nv_bfloat162 th = __halves2bfloat162(h0, h1);
    __nv_bfloat162 tl = __halves2bfloat162(l0, l1);
    hp = *reinterpret_cast<uint32_t*>(&th);
    lp = *reinterpret_cast<uint32_t*>(&tl);
}

// ===========================================================================
// Shared GEMM tile geometry: CTA 128x128, BK=32, single-buffered static smem.
// 8 warps: wr = warp>>1 (m 32-block), wc = warp&1 (n 64-block).
// A [m][k] staged packed (attention-Q pattern); B transposed in staging to
// [n][k] rows (attention-K pattern). All ldmatrix addressing verbatim from
// the proven attention kernel.
// ===========================================================================
#define KP 40          // halves per smem row (80 B)
#define TSZ (128 * KP) // 5120 halves = 10240 B per array

struct GemmSmem {
    __align__(16) __nv_bfloat16 Ah[TSZ];
    __align__(16) __nv_bfloat16 Al[TSZ];
    __align__(16) __nv_bfloat16 Bh[TSZ];
    __align__(16) __nv_bfloat16 Bl[TSZ];
};

// Stage + compute body shared by both GEMMs via macro-free duplication below.

// ===========================================================================
// Kernel 1: QKV projection. C[8192 x 1536] = x @ [Wq|Wkv]; f32 scatter to
// g_q/g_k/g_v in [b,h,n,d] (R3/R5-proven epilogue mapping).
// ===========================================================================
__global__ __launch_bounds__(256) void qkv_mma_kernel(
    const float* __restrict__ x, const float* __restrict__ Wq, const float* __restrict__ Wkv)
{
    __shared__ GemmSmem s;
    const uint32_t sAh = smem_to_u32(s.Ah);
    const uint32_t sAl = smem_to_u32(s.Al);
    const uint32_t sBh = smem_to_u32(s.Bh);
    const uint32_t sBl = smem_to_u32(s.Bl);

    const int tid = threadIdx.x, lane = tid & 31, w = tid >> 5;
    const int wr = w >> 1, wc = w & 1;
    const int row0 = blockIdx.y * 128, col0 = blockIdx.x * 128;

    const float* W; int wld, wc0;
    if (col0 < 512) { W = Wq;  wld = 512;  wc0 = col0; }
    else            { W = Wkv; wld = 1024; wc0 = col0 - 512; }

    // staging maps
    const int ar = tid >> 1, akc = (tid & 1) * 16;    // A: 128 m-rows x 2 half-k
    const int br = tid >> 3, bn = (tid & 7) * 16;     // B: 32 k-rows x 8 n-chunks

    const float* pA = x + (size_t)(row0 + ar) * DIN + akc;
    const float* pB = W + (size_t)br * wld + wc0 + bn;

    float acc[2][8][4];
#pragma unroll
    for (int m = 0; m < 2; m++)
#pragma unroll
        for (int n = 0; n < 8; n++)
#pragma unroll
            for (int c = 0; c < 4; c++) acc[m][n][c] = 0.f;

    float4 xa[4], bw[4];
#pragma unroll
    for (int v = 0; v < 4; v++) {
        xa[v] = *(const float4*)(pA + v * 4);
        bw[v] = *(const float4*)(pB + v * 4);
    }

    for (int kt = 0; kt < 16; kt++) {
        __syncthreads();   // previous compute done before restaging
        // ---- stage A (packed hi/lo, [m][k]) ----
        {
            uint32_t hp[8], lp[8];
#pragma unroll
            for (int v = 0; v < 4; v++) {
                split2_pack(xa[v].x, xa[v].y, hp[v * 2],     lp[v * 2]);
                split2_pack(xa[v].z, xa[v].w, hp[v * 2 + 1], lp[v * 2 + 1]);
            }
            const uint32_t so = (uint32_t)(ar * KP + akc) * 2;
            *(uint4*)((char*)s.Ah + so)      = make_uint4(hp[0], hp[1], hp[2], hp[3]);
            *(uint4*)((char*)s.Ah + so + 16) = make_uint4(hp[4], hp[5], hp[6], hp[7]);
            *(uint4*)((char*)s.Al + so)      = make_uint4(lp[0], lp[1], lp[2], lp[3]);
            *(uint4*)((char*)s.Al + so + 16) = make_uint4(lp[4], lp[5], lp[6], lp[7]);
        }
        // ---- stage B transposed ([n][k] rows, scalar split stores) ----
#pragma unroll
        for (int v = 0; v < 4; v++) {
            const float vals[4] = {bw[v].x, bw[v].y, bw[v].z, bw[v].w};
#pragma unroll
            for (int c = 0; c < 4; c++) {
                __nv_bfloat16 hh, ll;
                split_bf16(vals[c], hh, ll);
                const int nrow = bn + v * 4 + c;
                s.Bh[nrow * KP + br] = hh;
                s.Bl[nrow * KP + br] = ll;
            }
        }
        __syncthreads();

        if (kt < 15) {
            const int ko = (kt + 1) * 32;
#pragma unroll
            for (int v = 0; v < 4; v++) {
                xa[v] = *(const float4*)(pA + ko + v * 4);
                bw[v] = *(const float4*)(pB + (size_t)ko * wld + v * 4);
            }
        }

        // ---- compute: verbatim attention fragment addressing ----
#pragma unroll
        for (int ks = 0; ks < 2; ks++) {
            uint32_t ah[2][4], al[2][4];
#pragma unroll
            for (int m = 0; m < 2; m++) {
                const uint32_t aoff =
                    (uint32_t)((32 * wr + 16 * m + (lane & 15)) * KP + ks * 16 + (lane >> 4) * 8) * 2;
                ldmx4(ah[m], sAh + aoff);
                ldmx4(al[m], sAl + aoff);
            }
#pragma unroll
            for (int n = 0; n < 8; n++) {
                uint32_t bh[2], bl[2];
                const uint32_t boff =
                    (uint32_t)((64 * wc + n * 8 + (lane & 7)) * KP + ks * 16 + ((lane >> 3) & 1) * 8) * 2;
                ldmx2(bh, sBh + boff);
                ldmx2(bl, sBl + boff);
#pragma unroll
                for (int m = 0; m < 2; m++) {
                    mma16816(acc[m][n], ah[m], bh);
                    mma16816(acc[m][n], al[m], bh);
                    mma16816(acc[m][n], ah[m], bl);
                }
            }
        }
    }

    // ---- epilogue: f32 scatter into q/k/v [b,h,n,d] ----
    const int g = lane >> 2, tg = lane & 3;
    const int cbase = col0 + 64 * wc;
    float* dst; int cc0;
    if (cbase < 512)       { dst = g_q; cc0 = cbase; }
    else if (cbase < 1024) { dst = g_k; cc0 = cbase - 512; }
    else                   { dst = g_v; cc0 = cbase - 1024; }
    const int hh = cc0 >> 6;
#pragma unroll
    for (int m = 0; m < 2; m++) {
        const int rA = row0 + 32 * wr + 16 * m + g;
        const int rB = rA + 8;
        float* pA1 = dst + ((size_t)((rA >> 10) * NUM_H + hh) * NUM_N + (rA & 1023)) * DHEAD;
        float* pB1 = dst + ((size_t)((rB >> 10) * NUM_H + hh) * NUM_N + (rB & 1023)) * DHEAD;
#pragma unroll
        for (int n = 0; n < 8; n++) {
            const int d = n * 8 + tg * 2;
            *reinterpret_cast<float2*>(pA1 + d) = make_float2(acc[m][n][0], acc[m][n][1]);
            *reinterpret_cast<float2*>(pB1 + d) = make_float2(acc[m][n][2], acc[m][n][3]);
        }
    }
}

// ===========================================================================
// Kernel 1b: bias transpose  [b][i][j][h] -> [b][h][i][j]  (verbatim R5)
// ===========================================================================
__global__ __launch_bounds__(256) void bias_transpose_kernel(const float* __restrict__ in)
{
    __shared__ float sm[8 * 32 * 33];
    const int tid = threadIdx.x;
    const int j0 = blockIdx.x * 32;
    const int i0 = blockIdx.y * 32;
    const int b  = blockIdx.z;
#pragma unroll
    for (int k = 0; k < 8; k++) {
        const int idx = tid + k * 256;
        const int ii = idx >> 6;
        const int f  = idx & 63;
        const float4 v = *reinterpret_cast<const float4*>(
            in + (((size_t)b * NUM_N + i0 + ii) * NUM_N + j0) * NUM_H + f * 4);
        const int jj = f >> 1;
        const int h0 = (f & 1) * 4;
        sm[(h0 + 0) * (32 * 33) + ii * 33 + jj] = v.x;
        sm[(h0 + 1) * (32 * 33) + ii * 33 + jj] = v.y;
        sm[(h0 + 2) * (32 * 33) + ii * 33 + jj] = v.z;
        sm[(h0 + 3) * (32 * 33) + ii * 33 + jj] = v.w;
    }
    __syncthreads();
#pragma unroll
    for (int k = 0; k < 8; k++) {
        const int idx = tid + k * 256;
        const int rowid = idx >> 3;
        const int h  = rowid >> 5;
        const int ii = rowid & 31;
        const int jj0 = (idx & 7) * 4;
        float4 v;
        v.x = sm[h * (32 * 33) + ii * 33 + jj0 + 0];
        v.y = sm[h * (32 * 33) + ii * 33 + jj0 + 1];
        v.z = sm[h * (32 * 33) + ii * 33 + jj0 + 2];
        v.w = sm[h * (32 * 33) + ii * 33 + jj0 + 3];
        *reinterpret_cast<float4*>(
            g_biasT + (((size_t)(b * NUM_H + h) * NUM_N) + i0 + ii) * NUM_N + j0 + jj0) = v;
    }
}

// ===========================================================================
// Kernel 2: warp-MMA flash attention (verbatim R5 — passed at 749.7us)
// ===========================================================================
#define AT_QHI  0
#define AT_QLO  18432
#define AT_KHI  36864
#define AT_KLO  46080
#define AT_VHI  55296
#define AT_VLO  64512
#define AT_MK   73728
#define AT_TOTAL 73984
#define PAD 72

__global__ __launch_bounds__(128) void attn_mma_kernel(const int* __restrict__ mask)
{
    extern __shared__ char smem[];
    const uint32_t sb = smem_to_u32(smem);
    const int tid  = threadIdx.x;
    const int lane = tid & 31;
    const int w    = tid >> 5;
    const int i0   = blockIdx.x * 128;
    const int h    = blockIdx.y;
    const int bz   = blockIdx.z;

    {
        const float* qg = g_q + ((size_t)(bz * NUM_H + h) * NUM_N + i0 + tid) * DHEAD;
        float qv[64];
#pragma unroll
        for (int u = 0; u < 16; u++) {
            float4 t = *reinterpret_cast<const float4*>(qg + u * 4);
            qv[u*4+0] = t.x; qv[u*4+1] = t.y; qv[u*4+2] = t.z; qv[u*4+3] = t.w;
        }
#pragma unroll
        for (int cp = 0; cp < 32; cp++) {
            __nv_bfloat16 h0, l0, h1, l1;
            split_bf16(qv[2*cp],   h0, l0);
            split_bf16(qv[2*cp+1], h1, l1);
            const uint32_t off = (uint32_t)(tid * PAD + 2 * cp) * 2;
            *reinterpret_cast<__nv_bfloat162*>(smem + AT_QHI + off) = __halves2bfloat162(h0, h1);
            *reinterpret_cast<__nv_bfloat162*>(smem + AT_QLO + off) = __halves2bfloat162(l0, l1);
        }
    }

    const int g  = lane >> 2;
    const int tg = lane & 3;
    const int arow = (lane & 15);
    const int acol = (lane >> 4) * 8;
    const int brow = (lane & 7);
    const int bcol = ((lane >> 3) & 1) * 8;

    float O[2][8][4];
#pragma unroll
    for (int m = 0; m < 2; m++)
#pragma unroll
        for (int n = 0; n < 8; n++)
#pragma unroll
            for (int c = 0; c < 4; c++) O[m][n][c] = 0.f;
    float lsum[2][2] = {{0.f, 0.f}, {0.f, 0.f}};

    const int krow = tid >> 1;
    const int kc0  = (tid & 1) * 32;
    float* mk = reinterpret_cast<float*>(smem + AT_MK);

    for (int jt = 0; jt < 16; jt++) {
        const int j0 = jt * 64;
        __syncthreads();

        {
            const float* kgp = g_k + ((size_t)(bz * NUM_H + h) * NUM_N + j0 + krow) * DHEAD + kc0;
            const float* vgp = g_v + ((size_t)(bz * NUM_H + h) * NUM_N + j0 + krow) * DHEAD + kc0;
            float kv[32], vv[32];
#pragma unroll
            for (int u = 0; u < 8; u++) {
                float4 t = *reinterpret_cast<const float4*>(kgp + u * 4);
                kv[u*4+0]=t.x; kv[u*4+1]=t.y; kv[u*4+2]=t.z; kv[u*4+3]=t.w;
                float4 s = *reinterpret_cast<const float4*>(vgp + u * 4);
                vv[u*4+0]=s.x; vv[u*4+1]=s.y; vv[u*4+2]=s.z; vv[u*4+3]=s.w;
            }
#pragma unroll
            for (int cp = 0; cp < 16; cp++) {
                const uint32_t off = (uint32_t)(krow * PAD + kc0 + 2 * cp) * 2;
                __nv_bfloat16 h0, l0, h1, l1;
                split_bf16(kv[2*cp],   h0, l0);
                split_bf16(kv[2*cp+1], h1, l1);
                *reinterpret_cast<__nv_bfloat162*>(smem + AT_KHI + off) = __halves2bfloat162(h0, h1);
                *reinterpret_cast<__nv_bfloat162*>(smem + AT_KLO + off) = __halves2bfloat162(l0, l1);
                split_bf16(vv[2*cp],   h0, l0);
                split_bf16(vv[2*cp+1], h1, l1);
                *reinterpret_cast<__nv_bfloat162*>(smem + AT_VHI + off) = __halves2bfloat162(h0, h1);
                *reinterpret_cast<__nv_bfloat162*>(smem + AT_VLO + off) = __halves2bfloat162(l0, l1);
            }
        }
        if (tid < 64) mk[tid] = mask[bz * NUM_N + j0 + tid] ? 1.f : 0.f;
        __syncthreads();

        float S[2][8][4];
#pragma unroll
        for (int m = 0; m < 2; m++)
#pragma unroll
            for (int n = 0; n < 8; n++)
#pragma unroll
                for (int c = 0; c < 4; c++) S[m][n][c] = 0.f;

#pragma unroll
        for (int ks = 0; ks < 4; ks++) {
            uint32_t ah[2][4], al[2][4];
#pragma unroll
            for (int m = 0; m < 2; m++) {
                const uint32_t aoff = sb + AT_QHI +
                    (uint32_t)((32 * w + 16 * m + arow) * PAD + ks * 16 + acol) * 2;
                ldmx4(ah[m], aoff);
                ldmx4(al[m], aoff + (AT_QLO - AT_QHI));
            }
#pragma unroll
            for (int n = 0; n < 8; n++) {
                uint32_t bh[2], bl[2];
                const uint32_t boff = sb + AT_KHI +
                    (uint32_t)((n * 8 + brow) * PAD + ks * 16 + bcol) * 2;
                ldmx2(bh, boff);
                ldmx2(bl, boff + (AT_KLO - AT_KHI));
#pragma unroll
                for (int m = 0; m < 2; m++) {
                    mma16816(S[m][n], ah[m], bh);
                    mma16816(S[m][n], al[m], bh);
                    mma16816(S[m][n], ah[m], bl);
                }
            }
        }

        uint32_t ph[2][4][4], pl[2][4][4];
#pragma unroll
        for (int m = 0; m < 2; m++) {
            const int r1 = i0 + 32 * w + 16 * m + g;
            const float* bp1 = g_biasT + ((size_t)(bz * NUM_H + h) * NUM_N + r1) * NUM_N + j0 + tg * 2;
            const float* bp2 = bp1 + 8 * NUM_N;
#pragma unroll
            for (int n = 0; n < 8; n++) {
                const float2 bb1 = *reinterpret_cast<const float2*>(bp1 + n * 8);
                const float2 bb2 = *reinterpret_cast<const float2*>(bp2 + n * 8);
                const float2 mm  = *reinterpret_cast<const float2*>(mk + n * 8 + tg * 2);
                const float p0 = mm.x * __expf(fmaf(S[m][n][0], QK_SCALE, bb1.x));
                const float p1 = mm.y * __expf(fmaf(S[m][n][1], QK_SCALE, bb1.y));
                const float p2 = mm.x * __expf(fmaf(S[m][n][2], QK_SCALE, bb2.x));
                const float p3 = mm.y * __expf(fmaf(S[m][n][3], QK_SCALE, bb2.y));
                lsum[m][0] += p0 + p1;
                lsum[m][1] += p2 + p3;
                const int kc = n >> 1;
                const int rb = (n & 1) * 2;
                __nv_bfloat16 hx, lx, hy, ly;
                split_bf16(p0, hx, lx); split_bf16(p1, hy, ly);
                ph[m][kc][rb]   = packbf2(__bfloat162float(hx), __bfloat162float(hy));
                pl[m][kc][rb]   = packbf2(__bfloat162float(lx), __bfloat162float(ly));
                split_bf16(p2, hx, lx); split_bf16(p3, hy, ly);
                ph[m][kc][rb+1] = packbf2(__bfloat162float(hx), __bfloat162float(hy));
                pl[m][kc][rb+1] = packbf2(__bfloat162float(lx), __bfloat162float(ly));
            }
        }

#pragma unroll
        for (int kc = 0; kc < 4; kc++) {
#pragma unroll
            for (int n = 0; n < 8; n++) {
                uint32_t vh[2], vl[2];
                const uint32_t voff = sb + AT_VHI +
                    (uint32_t)((kc * 16 + (lane & 15)) * PAD + n * 8) * 2;
                ldmx2t(vh, voff);
                ldmx2t(vl, voff + (AT_VLO - AT_VHI));
#pragma unroll
                for (int m = 0; m < 2; m++) {
                    mma16816(O[m][n], ph[m][kc], vh);
                    mma16816(O[m][n], ph[m][kc], vl);
                    mma16816(O[m][n], pl[m][kc], vh);
                }
            }
        }
    }

#pragma unroll
    for (int m = 0; m < 2; m++)
#pragma unroll
        for (int r = 0; r < 2; r++) {
            lsum[m][r] += __shfl_xor_sync(0xffffffffu, lsum[m][r], 1);
            lsum[m][r] += __shfl_xor_sync(0xffffffffu, lsum[m][r], 2);
        }
#pragma unroll
    for (int m = 0; m < 2; m++) {
        const int r1 = i0 + 32 * w + 16 * m + g;
        const float inv1 = 1.f / lsum[m][0];
        const float inv2 = 1.f / lsum[m][1];
        float* o1 = g_att + ((size_t)bz * NUM_N + r1) * DINNER + h * DHEAD + tg * 2;
        float* o2 = o1 + 8 * DINNER;
#pragma unroll
        for (int n = 0; n < 8; n++) {
            *reinterpret_cast<float2*>(o1 + n * 8) = make_float2(O[m][n][0] * inv1, O[m][n][1] * inv1);
            *reinterpret_cast<float2*>(o2 + n * 8) = make_float2(O[m][n][2] * inv2, O[m][n][3] * inv2);
        }
    }
}

// ===========================================================================
// Kernel 3: output projection. out = g_att @ Wout + bout (same GEMM pattern)
// ===========================================================================
__global__ __launch_bounds__(256) void out_mma_kernel(
    const float* __restrict__ Wout, const float* __restrict__ bout, float* __restrict__ out)
{
    __shared__ GemmSmem s;
    const uint32_t sAh = smem_to_u32(s.Ah);
    const uint32_t sAl = smem_to_u32(s.Al);
    const uint32_t sBh = smem_to_u32(s.Bh);
    const uint32_t sBl = smem_to_u32(s.Bl);

    const int tid = threadIdx.x, lane = tid & 31, w = tid >> 5;
    const int wr = w >> 1, wc = w & 1;
    const int row0 = blockIdx.y * 128, col0 = blockIdx.x * 128;

    const int ar = tid >> 1, akc = (tid & 1) * 16;
    const int br = tid >> 3, bn = (tid & 7) * 16;

    const float* pA = g_att + (size_t)(row0 + ar) * DINNER + akc;
    const float* pB = Wout + (size_t)br * DOUT + col0 + bn;

    float acc[2][8][4];
#pragma unroll
    for (int m = 0; m < 2; m++)
#pragma unroll
        for (int n = 0; n < 8; n++)
#pragma unroll
            for (int c = 0; c < 4; c++) acc[m][n][c] = 0.f;

    float4 xa[4], bw[4];
#pragma unroll
    for (int v = 0; v < 4; v++) {
        xa[v] = *(const float4*)(pA + v * 4);
        bw[v] = *(const float4*)(pB + v * 4);
    }

    for (int kt = 0; kt < 16; kt++) {
        __syncthreads();
        {
            uint32_t hp[8], lp[8];
#pragma unroll
            for (int v = 0; v < 4; v++) {
                split2_pack(xa[v].x, xa[v].y, hp[v * 2],     lp[v * 2]);
                split2_pack(xa[v].z, xa[v].w, hp[v * 2 + 1], lp[v * 2 + 1]);
            }
            const uint32_t so = (uint32_t)(ar * KP + akc) * 2;
            *(uint4*)((char*)s.Ah + so)      = make_uint4(hp[0], hp[1], hp[2], hp[3]);
            *(uint4*)((char*)s.Ah + so + 16) = make_uint4(hp[4], hp[5], hp[6], hp[7]);
            *(uint4*)((char*)s.Al + so)      = make_uint4(lp[0], lp[1], lp[2], lp[3]);
            *(uint4*)((char*)s.Al + so + 16) = make_uint4(lp[4], lp[5], lp[6], lp[7]);
        }
#pragma unroll
        for (int v = 0; v < 4; v++) {
            const float vals[4] = {bw[v].x, bw[v].y, bw[v].z, bw[v].w};
#pragma unroll
            for (int c = 0; c < 4; c++) {
                __nv_bfloat16 hh, ll;
                split_bf16(vals[c], hh, ll);
                const int nrow = bn + v * 4 + c;
                s.Bh[nrow * KP + br] = hh;
                s.Bl[nrow * KP + br] = ll;
            }
        }
        __syncthreads();

        if (kt < 15) {
            const int ko = (kt + 1) * 32;
#pragma unroll
            for (int v = 0; v < 4; v++) {
                xa[v] = *(const float4*)(pA + ko + v * 4);
                bw[v] = *(const float4*)(pB + (size_t)ko * DOUT + v * 4);
            }
        }

#pragma unroll
        for (int ks = 0; ks < 2; ks++) {
            uint32_t ah[2][4], al[2][4];
#pragma unroll
            for (int m = 0; m < 2; m++) {
                const uint32_t aoff =
                    (uint32_t)((32 * wr + 16 * m + (lane & 15)) * KP + ks * 16 + (lane >> 4) * 8) * 2;
                ldmx4(ah[m], sAh + aoff);
                ldmx4(al[m], sAl + aoff);
            }
#pragma unroll
            for (int n = 0; n < 8; n++) {
                uint32_t bh[2], bl[2];
                const uint32_t boff =
                    (uint32_t)((64 * wc + n * 8 + (lane & 7)) * KP + ks * 16 + ((lane >> 3) & 1) * 8) * 2;
                ldmx2(bh, sBh + boff);
                ldmx2(bl, sBl + boff);
#pragma unroll
                for (int m = 0; m < 2; m++) {
                    mma16816(acc[m][n], ah[m], bh);
                    mma16816(acc[m][n], al[m], bh);
                    mma16816(acc[m][n], ah[m], bl);
                }
            }
        }
    }

    const int g = lane >> 2, tg = lane & 3;
#pragma unroll
    for (int m = 0; m < 2; m++) {
        const int rA = row0 + 32 * wr + 16 * m + g;
        const int rB = rA + 8;
#pragma unroll
        for (int n = 0; n < 8; n++) {
            const int c = col0 + 64 * wc + n * 8 + tg * 2;
            const float2 bv = *reinterpret_cast<const float2*>(bout + c);
            *reinterpret_cast<float2*>(out + (size_t)rA * DOUT + c) =
                make_float2(acc[m][n][0] + bv.x, acc[m][n][1] + bv.y);
            *reinterpret_cast<float2*>(out + (size_t)rB * DOUT + c) =
                make_float2(acc[m][n][2] + bv.x, acc[m][n][3] + bv.y);
        }
    }
}

// ---------------------------------------------------------------------------
extern "C" void kernel_launch(void* const* d_in, const int* in_sizes, int n_in,
                              void* d_out, int out_size)
{
    const float* x    = (const float*)d_in[0];
    const int*   mask = (const int*)  d_in[1];
    const float* sb   = (const float*)d_in[2];
    const float* Wq   = (const float*)d_in[3];
    const float* Wkv  = (const float*)d_in[4];
    const float* Wout = (const float*)d_in[5];
    const float* bout = (const float*)d_in[6];
    float* out = (float*)d_out;

    // 1) QKV projection (bf16-split warp MMA, static smem, direct inputs)
    qkv_mma_kernel<<<dim3(12, 64), 256>>>(x, Wq, Wkv);

    // 1b) bias transpose
    bias_transpose_kernel<<<dim3(32, 32, NUM_B), 256>>>(sb);

    // 2) warp-MMA flash attention (verbatim R5)
    cudaFuncSetAttribute(attn_mma_kernel, cudaFuncAttributeMaxDynamicSharedMemorySize, AT_TOTAL);
    attn_mma_kernel<<<dim3(NUM_N / 128, NUM_H, NUM_B), 128, AT_TOTAL>>>(mask);

    // 3) output projection (bf16-split warp MMA, static smem)
    out_mma_kernel<<<dim3(4, 64), 256>>>(Wout, bout, out);
}

// round 9
// speedup vs baseline: 6.1559x; 1.3163x over previous
#include <cuda_runtime.h>
#include <cuda_bf16.h>
#include <cstdint>
#include <cstddef>

#define NUM_B   8
#define NUM_N   1024
#define NUM_H   8
#define DHEAD   64
#define DIN     512
#define DINNER  512
#define DOUT    512
#define QK_SCALE 0.125f

// Scratch (allocation-free: device globals)
__device__ float g_q[NUM_B * NUM_H * NUM_N * DHEAD];
__device__ float g_k[NUM_B * NUM_H * NUM_N * DHEAD];
__device__ float g_v[NUM_B * NUM_H * NUM_N * DHEAD];
__device__ float g_att[NUM_B * NUM_N * DINNER];
__device__ float g_biasT[(size_t)NUM_B * NUM_H * NUM_N * NUM_N];   // [b][h][i][j]

// ===========================================================================
// helpers
// ===========================================================================
__device__ __forceinline__ uint32_t smem_to_u32(const void* p) {
    uint32_t a;
    asm("{ .reg .u64 t; cvta.to.shared.u64 t, %1; cvt.u32.u64 %0, t; }" : "=r"(a) : "l"(p));
    return a;
}
__device__ __forceinline__ void ldmx4(uint32_t* r, uint32_t addr) {
    asm volatile("ldmatrix.sync.aligned.m8n8.x4.shared.b16 {%0,%1,%2,%3}, [%4];"
        : "=r"(r[0]), "=r"(r[1]), "=r"(r[2]), "=r"(r[3]) : "r"(addr));
}
__device__ __forceinline__ void ldmx2(uint32_t* r, uint32_t addr) {
    asm volatile("ldmatrix.sync.aligned.m8n8.x2.shared.b16 {%0,%1}, [%2];"
        : "=r"(r[0]), "=r"(r[1]) : "r"(addr));
}
__device__ __forceinline__ void ldmx2t(uint32_t* r, uint32_t addr) {
    asm volatile("ldmatrix.sync.aligned.m8n8.x2.trans.shared.b16 {%0,%1}, [%2];"
        : "=r"(r[0]), "=r"(r[1]) : "r"(addr));
}
__device__ __forceinline__ void mma16816(float* c, const uint32_t* a, const uint32_t* b) {
    asm volatile("mma.sync.aligned.m16n8k16.row.col.f32.bf16.bf16.f32 "
        "{%0,%1,%2,%3}, {%4,%5,%6,%7}, {%8,%9}, {%0,%1,%2,%3};"
        : "+f"(c[0]), "+f"(c[1]), "+f"(c[2]), "+f"(c[3])
        : "r"(a[0]), "r"(a[1]), "r"(a[2]), "r"(a[3]), "r"(b[0]), "r"(b[1]));
}
__device__ __forceinline__ void mma2(float* c, const uint32_t* a, uint32_t b0, uint32_t b1) {
    asm volatile("mma.sync.aligned.m16n8k16.row.col.f32.bf16.bf16.f32 "
        "{%0,%1,%2,%3}, {%4,%5,%6,%7}, {%8,%9}, {%0,%1,%2,%3};"
        : "+f"(c[0]), "+f"(c[1]), "+f"(c[2]), "+f"(c[3])
        : "r"(a[0]), "r"(a[1]), "r"(a[2]), "r"(a[3]), "r"(b0), "r"(b1));
}
__device__ __forceinline__ void split_bf16(float x, __nv_bfloat16& hi, __nv_bfloat16& lo) {
    hi = __float2bfloat16_rn(x);
    lo = __float2bfloat16_rn(x - __bfloat162float(hi));
}
__device__ __forceinline__ uint32_t packbf2(float x, float y) {
    __nv_bfloat162 t = __floats2bfloat162_rn(x, y);   // x -> low half
    return *reinterpret_cast<uint32_t*>(&t);
}
__device__ __forceinline__ void split2_pack(float a, float b, uint32_t& hp, uint32_t& lp) {
    __nv_bfloat16 h0, l0, h1, l1;
    split_bf16(a, h0, l0); split_bf16(b, h1, l1);
    __nv_bfloat162 th = __halves2bfloat162(h0, h1);
    __nv_bfloat162 tl = __halves2bfloat162(l0, l1);
    hp = *reinterpret_cast<uint32_t*>(&th);
    lp = *reinterpret_cast<uint32_t*>(&tl);
}

// ===========================================================================
// GEMM tile geometry: CTA 128x128, BK=16, DOUBLE-buffered static smem (48 KB).
// 8 warps: wr = warp>>1 (32 m-rows), wc = warp&1 (64 n-cols).
// A [m][k] (attention-Q pattern), B transposed to [n][k] (attention-K pattern).
// ===========================================================================
#define KP2 24                  // halves per row (16 k + 8 pad) -> 48B rows
#define T2  (128 * KP2)         // 3072 halves = 6144 B per buffer per array

struct GemmSmem2 {
    __align__(16) __nv_bfloat16 Ah[2][T2];
    __align__(16) __nv_bfloat16 Al[2][T2];
    __align__(16) __nv_bfloat16 Bh[2][T2];
    __align__(16) __nv_bfloat16 Bl[2][T2];
};  // 49152 bytes total

// ===========================================================================
// Kernel 1: QKV projection. C[8192 x 1536] = x @ [Wq|Wkv]; f32 scatter to
// g_q/g_k/g_v in [b,h,n,d] (proven epilogue mapping).
// ===========================================================================
__global__ __launch_bounds__(256) void qkv_mma_kernel(
    const float* __restrict__ x, const float* __restrict__ Wq, const float* __restrict__ Wkv)
{
    __shared__ GemmSmem2 s;
    const int tid = threadIdx.x, lane = tid & 31, w = tid >> 5;
    const int wr = w >> 1, wc = w & 1;
    const int row0 = blockIdx.y * 128, col0 = blockIdx.x * 128;

    const float* W; int wld, wc0;
    if (col0 < 512) { W = Wq;  wld = 512;  wc0 = col0; }
    else            { W = Wkv; wld = 1024; wc0 = col0 - 512; }

    // A staging map: thread -> m-row ar, 8-k chunk
    const int ar = tid >> 1, akc = (tid & 1) * 8;
    const float* pA = x + (size_t)(row0 + ar) * DIN + akc;
    // B staging map: thread -> k-row br, strided n gather (nb + 16c)
    const int br = tid >> 4, nb = tid & 15;
    const float* pB = W + (size_t)br * wld + wc0 + nb;

    float acc[2][8][4];
#pragma unroll
    for (int m = 0; m < 2; m++)
#pragma unroll
        for (int n = 0; n < 8; n++)
#pragma unroll
            for (int c = 0; c < 4; c++) acc[m][n][c] = 0.f;

    float4 a0, a1;
    float bv[8];

    // prefetch tile 0
    a0 = *(const float4*)(pA);
    a1 = *(const float4*)(pA + 4);
#pragma unroll
    for (int c = 0; c < 8; c++) bv[c] = pB[16 * c];

    // stage tile 0 into buffer 0
    {
        uint32_t hp[4], lp[4];
        split2_pack(a0.x, a0.y, hp[0], lp[0]);
        split2_pack(a0.z, a0.w, hp[1], lp[1]);
        split2_pack(a1.x, a1.y, hp[2], lp[2]);
        split2_pack(a1.z, a1.w, hp[3], lp[3]);
        *(uint4*)&s.Ah[0][ar * KP2 + akc] = make_uint4(hp[0], hp[1], hp[2], hp[3]);
        *(uint4*)&s.Al[0][ar * KP2 + akc] = make_uint4(lp[0], lp[1], lp[2], lp[3]);
#pragma unroll
        for (int c = 0; c < 8; c++) {
            __nv_bfloat16 hh, ll;
            split_bf16(bv[c], hh, ll);
            s.Bh[0][(nb + 16 * c) * KP2 + br] = hh;
            s.Bl[0][(nb + 16 * c) * KP2 + br] = ll;
        }
    }
    __syncthreads();

    const uint32_t sAh0 = smem_to_u32(s.Ah[0]), sAl0 = smem_to_u32(s.Al[0]);
    const uint32_t sBh0 = smem_to_u32(s.Bh[0]), sBl0 = smem_to_u32(s.Bl[0]);
    const uint32_t bufStride = (uint32_t)T2 * 2;

    for (int kt = 0; kt < 32; kt++) {
        const int buf = kt & 1;
        const bool more = kt < 31;
        if (more) {
            const int k0 = (kt + 1) * 16;
            a0 = *(const float4*)(pA + k0);
            a1 = *(const float4*)(pA + k0 + 4);
#pragma unroll
            for (int c = 0; c < 8; c++) bv[c] = pB[(size_t)k0 * wld + 16 * c];
        }

        // ---- compute from buf ----
        {
            const uint32_t bofs = buf * bufStride;
            uint32_t ah[2][4], al[2][4];
#pragma unroll
            for (int m = 0; m < 2; m++) {
                const uint32_t aoff =
                    (uint32_t)((32 * wr + 16 * m + (lane & 15)) * KP2 + (lane >> 4) * 8) * 2;
                ldmx4(ah[m], sAh0 + bofs + aoff);
                ldmx4(al[m], sAl0 + bofs + aoff);
            }
#pragma unroll
            for (int nn = 0; nn < 4; nn++) {
                uint32_t th[4], tl[4];
                const uint32_t boff =
                    (uint32_t)((64 * wc + nn * 16 + (lane & 15)) * KP2 + (lane >> 4) * 8) * 2;
                ldmx4(th, sBh0 + bofs + boff);
                ldmx4(tl, sBl0 + bofs + boff);
#pragma unroll
                for (int m = 0; m < 2; m++) {
                    mma2(acc[m][2 * nn],     ah[m], th[0], th[2]);
                    mma2(acc[m][2 * nn],     al[m], th[0], th[2]);
                    mma2(acc[m][2 * nn],     ah[m], tl[0], tl[2]);
                    mma2(acc[m][2 * nn + 1], ah[m], th[1], th[3]);
                    mma2(acc[m][2 * nn + 1], al[m], th[1], th[3]);
                    mma2(acc[m][2 * nn + 1], ah[m], tl[1], tl[3]);
                }
            }
        }

        if (more) {
            const int nbuf = buf ^ 1;
            uint32_t hp[4], lp[4];
            split2_pack(a0.x, a0.y, hp[0], lp[0]);
            split2_pack(a0.z, a0.w, hp[1], lp[1]);
            split2_pack(a1.x, a1.y, hp[2], lp[2]);
            split2_pack(a1.z, a1.w, hp[3], lp[3]);
            *(uint4*)&s.Ah[nbuf][ar * KP2 + akc] = make_uint4(hp[0], hp[1], hp[2], hp[3]);
            *(uint4*)&s.Al[nbuf][ar * KP2 + akc] = make_uint4(lp[0], lp[1], lp[2], lp[3]);
#pragma unroll
            for (int c = 0; c < 8; c++) {
                __nv_bfloat16 hh, ll;
                split_bf16(bv[c], hh, ll);
                s.Bh[nbuf][(nb + 16 * c) * KP2 + br] = hh;
                s.Bl[nbuf][(nb + 16 * c) * KP2 + br] = ll;
            }
            __syncthreads();
        }
    }

    // ---- epilogue: f32 scatter into q/k/v [b,h,n,d] (proven) ----
    const int g = lane >> 2, tg = lane & 3;
    const int cbase = col0 + 64 * wc;
    float* dst; int cc0;
    if (cbase < 512)       { dst = g_q; cc0 = cbase; }
    else if (cbase < 1024) { dst = g_k; cc0 = cbase - 512; }
    else                   { dst = g_v; cc0 = cbase - 1024; }
    const int hh = cc0 >> 6;
#pragma unroll
    for (int m = 0; m < 2; m++) {
        const int rA = row0 + 32 * wr + 16 * m + g;
        const int rB = rA + 8;
        float* pA1 = dst + ((size_t)((rA >> 10) * NUM_H + hh) * NUM_N + (rA & 1023)) * DHEAD;
        float* pB1 = dst + ((size_t)((rB >> 10) * NUM_H + hh) * NUM_N + (rB & 1023)) * DHEAD;
#pragma unroll
        for (int n = 0; n < 8; n++) {
            const int d = n * 8 + tg * 2;
            *reinterpret_cast<float2*>(pA1 + d) = make_float2(acc[m][n][0], acc[m][n][1]);
            *reinterpret_cast<float2*>(pB1 + d) = make_float2(acc[m][n][2], acc[m][n][3]);
        }
    }
}

// ===========================================================================
// Kernel 1b: bias transpose  [b][i][j][h] -> [b][h][i][j]  (verbatim R8)
// ===========================================================================
__global__ __launch_bounds__(256) void bias_transpose_kernel(const float* __restrict__ in)
{
    __shared__ float sm[8 * 32 * 33];
    const int tid = threadIdx.x;
    const int j0 = blockIdx.x * 32;
    const int i0 = blockIdx.y * 32;
    const int b  = blockIdx.z;
#pragma unroll
    for (int k = 0; k < 8; k++) {
        const int idx = tid + k * 256;
        const int ii = idx >> 6;
        const int f  = idx & 63;
        const float4 v = *reinterpret_cast<const float4*>(
            in + (((size_t)b * NUM_N + i0 + ii) * NUM_N + j0) * NUM_H + f * 4);
        const int jj = f >> 1;
        const int h0 = (f & 1) * 4;
        sm[(h0 + 0) * (32 * 33) + ii * 33 + jj] = v.x;
        sm[(h0 + 1) * (32 * 33) + ii * 33 + jj] = v.y;
        sm[(h0 + 2) * (32 * 33) + ii * 33 + jj] = v.z;
        sm[(h0 + 3) * (32 * 33) + ii * 33 + jj] = v.w;
    }
    __syncthreads();
#pragma unroll
    for (int k = 0; k < 8; k++) {
        const int idx = tid + k * 256;
        const int rowid = idx >> 3;
        const int h  = rowid >> 5;
        const int ii = rowid & 31;
        const int jj0 = (idx & 7) * 4;
        float4 v;
        v.x = sm[h * (32 * 33) + ii * 33 + jj0 + 0];
        v.y = sm[h * (32 * 33) + ii * 33 + jj0 + 1];
        v.z = sm[h * (32 * 33) + ii * 33 + jj0 + 2];
        v.w = sm[h * (32 * 33) + ii * 33 + jj0 + 3];
        *reinterpret_cast<float4*>(
            g_biasT + (((size_t)(b * NUM_H + h) * NUM_N) + i0 + ii) * NUM_N + j0 + jj0) = v;
    }
}

// ===========================================================================
// Kernel 2: warp-MMA flash attention (verbatim R8 — passed at 690us)
// ===========================================================================
#define AT_QHI  0
#define AT_QLO  18432
#define AT_KHI  36864
#define AT_KLO  46080
#define AT_VHI  55296
#define AT_VLO  64512
#define AT_MK   73728
#define AT_TOTAL 73984
#define PAD 72

__global__ __launch_bounds__(128) void attn_mma_kernel(const int* __restrict__ mask)
{
    extern __shared__ char smem[];
    const uint32_t sb = smem_to_u32(smem);
    const int tid  = threadIdx.x;
    const int lane = tid & 31;
    const int w    = tid >> 5;
    const int i0   = blockIdx.x * 128;
    const int h    = blockIdx.y;
    const int bz   = blockIdx.z;

    {
        const float* qg = g_q + ((size_t)(bz * NUM_H + h) * NUM_N + i0 + tid) * DHEAD;
        float qv[64];
#pragma unroll
        for (int u = 0; u < 16; u++) {
            float4 t = *reinterpret_cast<const float4*>(qg + u * 4);
            qv[u*4+0] = t.x; qv[u*4+1] = t.y; qv[u*4+2] = t.z; qv[u*4+3] = t.w;
        }
#pragma unroll
        for (int cp = 0; cp < 32; cp++) {
            __nv_bfloat16 h0, l0, h1, l1;
            split_bf16(qv[2*cp],   h0, l0);
            split_bf16(qv[2*cp+1], h1, l1);
            const uint32_t off = (uint32_t)(tid * PAD + 2 * cp) * 2;
            *reinterpret_cast<__nv_bfloat162*>(smem + AT_QHI + off) = __halves2bfloat162(h0, h1);
            *reinterpret_cast<__nv_bfloat162*>(smem + AT_QLO + off) = __halves2bfloat162(l0, l1);
        }
    }

    const int g  = lane >> 2;
    const int tg = lane & 3;
    const int arow = (lane & 15);
    const int acol = (lane >> 4) * 8;
    const int brow = (lane & 7);
    const int bcol = ((lane >> 3) & 1) * 8;

    float O[2][8][4];
#pragma unroll
    for (int m = 0; m < 2; m++)
#pragma unroll
        for (int n = 0; n < 8; n++)
#pragma unroll
            for (int c = 0; c < 4; c++) O[m][n][c] = 0.f;
    float lsum[2][2] = {{0.f, 0.f}, {0.f, 0.f}};

    const int krow = tid >> 1;
    const int kc0  = (tid & 1) * 32;
    float* mk = reinterpret_cast<float*>(smem + AT_MK);

    for (int jt = 0; jt < 16; jt++) {
        const int j0 = jt * 64;
        __syncthreads();

        {
            const float* kgp = g_k + ((size_t)(bz * NUM_H + h) * NUM_N + j0 + krow) * DHEAD + kc0;
            const float* vgp = g_v + ((size_t)(bz * NUM_H + h) * NUM_N + j0 + krow) * DHEAD + kc0;
            float kv[32], vv[32];
#pragma unroll
            for (int u = 0; u < 8; u++) {
                float4 t = *reinterpret_cast<const float4*>(kgp + u * 4);
                kv[u*4+0]=t.x; kv[u*4+1]=t.y; kv[u*4+2]=t.z; kv[u*4+3]=t.w;
                float4 s = *reinterpret_cast<const float4*>(vgp + u * 4);
                vv[u*4+0]=s.x; vv[u*4+1]=s.y; vv[u*4+2]=s.z; vv[u*4+3]=s.w;
            }
#pragma unroll
            for (int cp = 0; cp < 16; cp++) {
                const uint32_t off = (uint32_t)(krow * PAD + kc0 + 2 * cp) * 2;
                __nv_bfloat16 h0, l0, h1, l1;
                split_bf16(kv[2*cp],   h0, l0);
                split_bf16(kv[2*cp+1], h1, l1);
                *reinterpret_cast<__nv_bfloat162*>(smem + AT_KHI + off) = __halves2bfloat162(h0, h1);
                *reinterpret_cast<__nv_bfloat162*>(smem + AT_KLO + off) = __halves2bfloat162(l0, l1);
                split_bf16(vv[2*cp],   h0, l0);
                split_bf16(vv[2*cp+1], h1, l1);
                *reinterpret_cast<__nv_bfloat162*>(smem + AT_VHI + off) = __halves2bfloat162(h0, h1);
                *reinterpret_cast<__nv_bfloat162*>(smem + AT_VLO + off) = __halves2bfloat162(l0, l1);
            }
        }
        if (tid < 64) mk[tid] = mask[bz * NUM_N + j0 + tid] ? 1.f : 0.f;
        __syncthreads();

        float S[2][8][4];
#pragma unroll
        for (int m = 0; m < 2; m++)
#pragma unroll
            for (int n = 0; n < 8; n++)
#pragma unroll
                for (int c = 0; c < 4; c++) S[m][n][c] = 0.f;

#pragma unroll
        for (int ks = 0; ks < 4; ks++) {
            uint32_t ah[2][4], al[2][4];
#pragma unroll
            for (int m = 0; m < 2; m++) {
                const uint32_t aoff = sb + AT_QHI +
                    (uint32_t)((32 * w + 16 * m + arow) * PAD + ks * 16 + acol) * 2;
                ldmx4(ah[m], aoff);
                ldmx4(al[m], aoff + (AT_QLO - AT_QHI));
            }
#pragma unroll
            for (int n = 0; n < 8; n++) {
                uint32_t bh[2], bl[2];
                const uint32_t boff = sb + AT_KHI +
                    (uint32_t)((n * 8 + brow) * PAD + ks * 16 + bcol) * 2;
                ldmx2(bh, boff);
                ldmx2(bl, boff + (AT_KLO - AT_KHI));
#pragma unroll
                for (int m = 0; m < 2; m++) {
                    mma16816(S[m][n], ah[m], bh);
                    mma16816(S[m][n], al[m], bh);
                    mma16816(S[m][n], ah[m], bl);
                }
            }
        }

        uint32_t ph[2][4][4], pl[2][4][4];
#pragma unroll
        for (int m = 0; m < 2; m++) {
            const int r1 = i0 + 32 * w + 16 * m + g;
            const float* bp1 = g_biasT + ((size_t)(bz * NUM_H + h) * NUM_N + r1) * NUM_N + j0 + tg * 2;
            const float* bp2 = bp1 + 8 * NUM_N;
#pragma unroll
            for (int n = 0; n < 8; n++) {
                const float2 bb1 = *reinterpret_cast<const float2*>(bp1 + n * 8);
                const float2 bb2 = *reinterpret_cast<const float2*>(bp2 + n * 8);
                const float2 mm  = *reinterpret_cast<const float2*>(mk + n * 8 + tg * 2);
                const float p0 = mm.x * __expf(fmaf(S[m][n][0], QK_SCALE, bb1.x));
                const float p1 = mm.y * __expf(fmaf(S[m][n][1], QK_SCALE, bb1.y));
                const float p2 = mm.x * __expf(fmaf(S[m][n][2], QK_SCALE, bb2.x));
                const float p3 = mm.y * __expf(fmaf(S[m][n][3], QK_SCALE, bb2.y));
                lsum[m][0] += p0 + p1;
                lsum[m][1] += p2 + p3;
                const int kc = n >> 1;
                const int rb = (n & 1) * 2;
                __nv_bfloat16 hx, lx, hy, ly;
                split_bf16(p0, hx, lx); split_bf16(p1, hy, ly);
                ph[m][kc][rb]   = packbf2(__bfloat162float(hx), __bfloat162float(hy));
                pl[m][kc][rb]   = packbf2(__bfloat162float(lx), __bfloat162float(ly));
                split_bf16(p2, hx, lx); split_bf16(p3, hy, ly);
                ph[m][kc][rb+1] = packbf2(__bfloat162float(hx), __bfloat162float(hy));
                pl[m][kc][rb+1] = packbf2(__bfloat162float(lx), __bfloat162float(ly));
            }
        }

#pragma unroll
        for (int kc = 0; kc < 4; kc++) {
#pragma unroll
            for (int n = 0; n < 8; n++) {
                uint32_t vh[2], vl[2];
                const uint32_t voff = sb + AT_VHI +
                    (uint32_t)((kc * 16 + (lane & 15)) * PAD + n * 8) * 2;
                ldmx2t(vh, voff);
                ldmx2t(vl, voff + (AT_VLO - AT_VHI));
#pragma unroll
                for (int m = 0; m < 2; m++) {
                    mma16816(O[m][n], ph[m][kc], vh);
                    mma16816(O[m][n], ph[m][kc], vl);
                    mma16816(O[m][n], pl[m][kc], vh);
                }
            }
        }
    }

#pragma unroll
    for (int m = 0; m < 2; m++)
#pragma unroll
        for (int r = 0; r < 2; r++) {
            lsum[m][r] += __shfl_xor_sync(0xffffffffu, lsum[m][r], 1);
            lsum[m][r] += __shfl_xor_sync(0xffffffffu, lsum[m][r], 2);
        }
#pragma unroll
    for (int m = 0; m < 2; m++) {
        const int r1 = i0 + 32 * w + 16 * m + g;
        const float inv1 = 1.f / lsum[m][0];
        const float inv2 = 1.f / lsum[m][1];
        float* o1 = g_att + ((size_t)bz * NUM_N + r1) * DINNER + h * DHEAD + tg * 2;
        float* o2 = o1 + 8 * DINNER;
#pragma unroll
        for (int n = 0; n < 8; n++) {
            *reinterpret_cast<float2*>(o1 + n * 8) = make_float2(O[m][n][0] * inv1, O[m][n][1] * inv1);
            *reinterpret_cast<float2*>(o2 + n * 8) = make_float2(O[m][n][2] * inv2, O[m][n][3] * inv2);
        }
    }
}

// ===========================================================================
// Kernel 3: output projection. out = g_att @ Wout + bout (double-buffered)
// ===========================================================================
__global__ __launch_bounds__(256) void out_mma_kernel(
    const float* __restrict__ Wout, const float* __restrict__ bout, float* __restrict__ out)
{
    __shared__ GemmSmem2 s;
    const int tid = threadIdx.x, lane = tid & 31, w = tid >> 5;
    const int wr = w >> 1, wc = w & 1;
    const int row0 = blockIdx.y * 128, col0 = blockIdx.x * 128;

    const int ar = tid >> 1, akc = (tid & 1) * 8;
    const float* pA = g_att + (size_t)(row0 + ar) * DINNER + akc;
    const int br = tid >> 4, nb = tid & 15;
    const float* pB = Wout + (size_t)br * DOUT + col0 + nb;

    float acc[2][8][4];
#pragma unroll
    for (int m = 0; m < 2; m++)
#pragma unroll
        for (int n = 0; n < 8; n++)
#pragma unroll
            for (int c = 0; c < 4; c++) acc[m][n][c] = 0.f;

    float4 a0, a1;
    float bv[8];
    a0 = *(const float4*)(pA);
    a1 = *(const float4*)(pA + 4);
#pragma unroll
    for (int c = 0; c < 8; c++) bv[c] = pB[16 * c];

    {
        uint32_t hp[4], lp[4];
        split2_pack(a0.x, a0.y, hp[0], lp[0]);
        split2_pack(a0.z, a0.w, hp[1], lp[1]);
        split2_pack(a1.x, a1.y, hp[2], lp[2]);
        split2_pack(a1.z, a1.w, hp[3], lp[3]);
        *(uint4*)&s.Ah[0][ar * KP2 + akc] = make_uint4(hp[0], hp[1], hp[2], hp[3]);
        *(uint4*)&s.Al[0][ar * KP2 + akc] = make_uint4(lp[0], lp[1], lp[2], lp[3]);
#pragma unroll
        for (int c = 0; c < 8; c++) {
            __nv_bfloat16 hh, ll;
            split_bf16(bv[c], hh, ll);
            s.Bh[0][(nb + 16 * c) * KP2 + br] = hh;
            s.Bl[0][(nb + 16 * c) * KP2 + br] = ll;
        }
    }
    __syncthreads();

    const uint32_t sAh0 = smem_to_u32(s.Ah[0]), sAl0 = smem_to_u32(s.Al[0]);
    const uint32_t sBh0 = smem_to_u32(s.Bh[0]), sBl0 = smem_to_u32(s.Bl[0]);
    const uint32_t bufStride = (uint32_t)T2 * 2;

    for (int kt = 0; kt < 32; kt++) {
        const int buf = kt & 1;
        const bool more = kt < 31;
        if (more) {
            const int k0 = (kt + 1) * 16;
            a0 = *(const float4*)(pA + k0);
            a1 = *(const float4*)(pA + k0 + 4);
#pragma unroll
            for (int c = 0; c < 8; c++) bv[c] = pB[(size_t)k0 * DOUT + 16 * c];
        }

        {
            const uint32_t bofs = buf * bufStride;
            uint32_t ah[2][4], al[2][4];
#pragma unroll
            for (int m = 0; m < 2; m++) {
                const uint32_t aoff =
                    (uint32_t)((32 * wr + 16 * m + (lane & 15)) * KP2 + (lane >> 4) * 8) * 2;
                ldmx4(ah[m], sAh0 + bofs + aoff);
                ldmx4(al[m], sAl0 + bofs + aoff);
            }
#pragma unroll
            for (int nn = 0; nn < 4; nn++) {
                uint32_t th[4], tl[4];
                const uint32_t boff =
                    (uint32_t)((64 * wc + nn * 16 + (lane & 15)) * KP2 + (lane >> 4) * 8) * 2;
                ldmx4(th, sBh0 + bofs + boff);
                ldmx4(tl, sBl0 + bofs + boff);
#pragma unroll
                for (int m = 0; m < 2; m++) {
                    mma2(acc[m][2 * nn],     ah[m], th[0], th[2]);
                    mma2(acc[m][2 * nn],     al[m], th[0], th[2]);
                    mma2(acc[m][2 * nn],     ah[m], tl[0], tl[2]);
                    mma2(acc[m][2 * nn + 1], ah[m], th[1], th[3]);
                    mma2(acc[m][2 * nn + 1], al[m], th[1], th[3]);
                    mma2(acc[m][2 * nn + 1], ah[m], tl[1], tl[3]);
                }
            }
        }

        if (more) {
            const int nbuf = buf ^ 1;
            uint32_t hp[4], lp[4];
            split2_pack(a0.x, a0.y, hp[0], lp[0]);
            split2_pack(a0.z, a0.w, hp[1], lp[1]);
            split2_pack(a1.x, a1.y, hp[2], lp[2]);
            split2_pack(a1.z, a1.w, hp[3], lp[3]);
            *(uint4*)&s.Ah[nbuf][ar * KP2 + akc] = make_uint4(hp[0], hp[1], hp[2], hp[3]);
            *(uint4*)&s.Al[nbuf][ar * KP2 + akc] = make_uint4(lp[0], lp[1], lp[2], lp[3]);
#pragma unroll
            for (int c = 0; c < 8; c++) {
                __nv_bfloat16 hh, ll;
                split_bf16(bv[c], hh, ll);
                s.Bh[nbuf][(nb + 16 * c) * KP2 + br] = hh;
                s.Bl[nbuf][(nb + 16 * c) * KP2 + br] = ll;
            }
            __syncthreads();
        }
    }

    const int g = lane >> 2, tg = lane & 3;
#pragma unroll
    for (int m = 0; m < 2; m++) {
        const int rA = row0 + 32 * wr + 16 * m + g;
        const int rB = rA + 8;
#pragma unroll
        for (int n = 0; n < 8; n++) {
            const int c = col0 + 64 * wc + n * 8 + tg * 2;
            const float2 bv2 = *reinterpret_cast<const float2*>(bout + c);
            *reinterpret_cast<float2*>(out + (size_t)rA * DOUT + c) =
                make_float2(acc[m][n][0] + bv2.x, acc[m][n][1] + bv2.y);
            *reinterpret_cast<float2*>(out + (size_t)rB * DOUT + c) =
                make_float2(acc[m][n][2] + bv2.x, acc[m][n][3] + bv2.y);
        }
    }
}

// ---------------------------------------------------------------------------
extern "C" void kernel_launch(void* const* d_in, const int* in_sizes, int n_in,
                              void* d_out, int out_size)
{
    const float* x    = (const float*)d_in[0];
    const int*   mask = (const int*)  d_in[1];
    const float* sb   = (const float*)d_in[2];
    const float* Wq   = (const float*)d_in[3];
    const float* Wkv  = (const float*)d_in[4];
    const float* Wout = (const float*)d_in[5];
    const float* bout = (const float*)d_in[6];
    float* out = (float*)d_out;

    // 1) QKV projection (double-buffered bf16-split warp MMA)
    qkv_mma_kernel<<<dim3(12, 64), 256>>>(x, Wq, Wkv);

    // 1b) bias transpose
    bias_transpose_kernel<<<dim3(32, 32, NUM_B), 256>>>(sb);

    // 2) warp-MMA flash attention (verbatim R8)
    cudaFuncSetAttribute(attn_mma_kernel, cudaFuncAttributeMaxDynamicSharedMemorySize, AT_TOTAL);
    attn_mma_kernel<<<dim3(NUM_N / 128, NUM_H, NUM_B), 128, AT_TOTAL>>>(mask);

    // 3) output projection (double-buffered bf16-split warp MMA)
    out_mma_kernel<<<dim3(4, 64), 256>>>(Wout, bout, out);
}

// round 11
// speedup vs baseline: 6.3536x; 1.0321x over previous
#include <cuda_runtime.h>
#include <cuda_bf16.h>
#include <cstdint>
#include <cstddef>

#define NUM_B   8
#define NUM_N   1024
#define NUM_H   8
#define DHEAD   64
#define DIN     512
#define DINNER  512
#define DOUT    512
#define QK_SCALE 0.125f

// Scratch (allocation-free: device globals)
__device__ __nv_bfloat16 g_qh[NUM_B * NUM_H * NUM_N * DHEAD];
__device__ __nv_bfloat16 g_ql[NUM_B * NUM_H * NUM_N * DHEAD];
__device__ __nv_bfloat16 g_kh[NUM_B * NUM_H * NUM_N * DHEAD];
__device__ __nv_bfloat16 g_kl[NUM_B * NUM_H * NUM_N * DHEAD];
__device__ __nv_bfloat16 g_vh[NUM_B * NUM_H * NUM_N * DHEAD];
__device__ __nv_bfloat16 g_vl[NUM_B * NUM_H * NUM_N * DHEAD];
__device__ float g_att[NUM_B * NUM_N * DINNER];
__device__ float g_biasT[(size_t)NUM_B * NUM_H * NUM_N * NUM_N];   // [b][h][i][j]

// ===========================================================================
// helpers
// ===========================================================================
__device__ __forceinline__ uint32_t smem_to_u32(const void* p) {
    uint32_t a;
    asm("{ .reg .u64 t; cvta.to.shared.u64 t, %1; cvt.u32.u64 %0, t; }" : "=r"(a) : "l"(p));
    return a;
}
__device__ __forceinline__ void ldmx4(uint32_t* r, uint32_t addr) {
    asm volatile("ldmatrix.sync.aligned.m8n8.x4.shared.b16 {%0,%1,%2,%3}, [%4];"
        : "=r"(r[0]), "=r"(r[1]), "=r"(r[2]), "=r"(r[3]) : "r"(addr));
}
__device__ __forceinline__ void ldmx2(uint32_t* r, uint32_t addr) {
    asm volatile("ldmatrix.sync.aligned.m8n8.x2.shared.b16 {%0,%1}, [%2];"
        : "=r"(r[0]), "=r"(r[1]) : "r"(addr));
}
__device__ __forceinline__ void ldmx2t(uint32_t* r, uint32_t addr) {
    asm volatile("ldmatrix.sync.aligned.m8n8.x2.trans.shared.b16 {%0,%1}, [%2];"
        : "=r"(r[0]), "=r"(r[1]) : "r"(addr));
}
__device__ __forceinline__ void mma16816(float* c, const uint32_t* a, const uint32_t* b) {
    asm volatile("mma.sync.aligned.m16n8k16.row.col.f32.bf16.bf16.f32 "
        "{%0,%1,%2,%3}, {%4,%5,%6,%7}, {%8,%9}, {%0,%1,%2,%3};"
        : "+f"(c[0]), "+f"(c[1]), "+f"(c[2]), "+f"(c[3])
        : "r"(a[0]), "r"(a[1]), "r"(a[2]), "r"(a[3]), "r"(b[0]), "r"(b[1]));
}
__device__ __forceinline__ void mma2(float* c, const uint32_t* a, uint32_t b0, uint32_t b1) {
    asm volatile("mma.sync.aligned.m16n8k16.row.col.f32.bf16.bf16.f32 "
        "{%0,%1,%2,%3}, {%4,%5,%6,%7}, {%8,%9}, {%0,%1,%2,%3};"
        : "+f"(c[0]), "+f"(c[1]), "+f"(c[2]), "+f"(c[3])
        : "r"(a[0]), "r"(a[1]), "r"(a[2]), "r"(a[3]), "r"(b0), "r"(b1));
}
__device__ __forceinline__ void split_bf16(float x, __nv_bfloat16& hi, __nv_bfloat16& lo) {
    hi = __float2bfloat16_rn(x);
    lo = __float2bfloat16_rn(x - __bfloat162float(hi));
}
__device__ __forceinline__ uint32_t packbf2(float x, float y) {
    __nv_bfloat162 t = __floats2bfloat162_rn(x, y);
    return *reinterpret_cast<uint32_t*>(&t);
}
__device__ __forceinline__ void split2_store(float a, float b, __nv_bfloat16* ph, __nv_bfloat16* pl) {
    __nv_bfloat16 h0, l0, h1, l1;
    split_bf16(a, h0, l0); split_bf16(b, h1, l1);
    *reinterpret_cast<__nv_bfloat162*>(ph) = __halves2bfloat162(h0, h1);
    *reinterpret_cast<__nv_bfloat162*>(pl) = __halves2bfloat162(l0, l1);
}
__device__ __forceinline__ void split2_pack(float a, float b, uint32_t& hp, uint32_t& lp) {
    __nv_bfloat16 h0, l0, h1, l1;
    split_bf16(a, h0, l0); split_bf16(b, h1, l1);
    __nv_bfloat162 th = __halves2bfloat162(h0, h1);
    __nv_bfloat162 tl = __halves2bfloat162(l0, l1);
    hp = *reinterpret_cast<uint32_t*>(&th);
    lp = *reinterpret_cast<uint32_t*>(&tl);
}

// ===========================================================================
// GEMM tile: CTA 128x128, BK=16, double-buffered static smem (48 KB).
// ===========================================================================
#define KP2 24
#define T2  (128 * KP2)

struct GemmSmem2 {
    __align__(16) __nv_bfloat16 Ah[2][T2];
    __align__(16) __nv_bfloat16 Al[2][T2];
    __align__(16) __nv_bfloat16 Bh[2][T2];
    __align__(16) __nv_bfloat16 Bl[2][T2];
};  // 49152 bytes

// Term-major compute macro body (shared shape for both GEMMs)
#define GEMM_COMPUTE(bofs)                                                          \
    {                                                                               \
        uint32_t ah[2][4], al[2][4], th[4][4], tl[4][4];                            \
        _Pragma("unroll")                                                           \
        for (int m = 0; m < 2; m++) {                                               \
            const uint32_t aoff =                                                   \
                (uint32_t)((32 * wr + 16 * m + (lane & 15)) * KP2 + (lane >> 4) * 8) * 2; \
            ldmx4(ah[m], sAh0 + (bofs) + aoff);                                     \
            ldmx4(al[m], sAl0 + (bofs) + aoff);                                     \
        }                                                                           \
        _Pragma("unroll")                                                           \
        for (int nn = 0; nn < 4; nn++) {                                            \
            const uint32_t boff =                                                   \
                (uint32_t)((64 * wc + nn * 16 + (lane & 15)) * KP2 + (lane >> 4) * 8) * 2; \
            ldmx4(th[nn], sBh0 + (bofs) + boff);                                    \
            ldmx4(tl[nn], sBl0 + (bofs) + boff);                                    \
        }                                                                           \
        _Pragma("unroll")                                                           \
        for (int nn = 0; nn < 4; nn++)                                              \
            _Pragma("unroll")                                                       \
            for (int m = 0; m < 2; m++) {                                           \
                mma2(acc[m][2 * nn],     ah[m], th[nn][0], th[nn][2]);              \
                mma2(acc[m][2 * nn + 1], ah[m], th[nn][1], th[nn][3]);              \
            }                                                                       \
        _Pragma("unroll")                                                           \
        for (int nn = 0; nn < 4; nn++)                                              \
            _Pragma("unroll")                                                       \
            for (int m = 0; m < 2; m++) {                                           \
                mma2(acc[m][2 * nn],     al[m], th[nn][0], th[nn][2]);              \
                mma2(acc[m][2 * nn + 1], al[m], th[nn][1], th[nn][3]);              \
            }                                                                       \
        _Pragma("unroll")                                                           \
        for (int nn = 0; nn < 4; nn++)                                              \
            _Pragma("unroll")                                                       \
            for (int m = 0; m < 2; m++) {                                           \
                mma2(acc[m][2 * nn],     ah[m], tl[nn][0], tl[nn][2]);              \
                mma2(acc[m][2 * nn + 1], ah[m], tl[nn][1], tl[nn][3]);              \
            }                                                                       \
    }

// ===========================================================================
// Kernel 1: QKV projection -> pre-split bf16 hi/lo q/k/v in [b,h,n,d]
// ===========================================================================
__global__ __launch_bounds__(256) void qkv_mma_kernel(
    const float* __restrict__ x, const float* __restrict__ Wq, const float* __restrict__ Wkv)
{
    __shared__ GemmSmem2 s;
    const int tid = threadIdx.x, lane = tid & 31, w = tid >> 5;
    const int wr = w >> 1, wc = w & 1;
    const int row0 = blockIdx.y * 128, col0 = blockIdx.x * 128;

    const float* W; int wld, wc0;
    if (col0 < 512) { W = Wq;  wld = 512;  wc0 = col0; }
    else            { W = Wkv; wld = 1024; wc0 = col0 - 512; }

    const int ar = tid >> 1, akc = (tid & 1) * 8;
    const float* pA = x + (size_t)(row0 + ar) * DIN + akc;
    const int br = tid >> 4, nb = tid & 15;
    const float* pB = W + (size_t)br * wld + wc0 + nb;

    float acc[2][8][4];
#pragma unroll
    for (int m = 0; m < 2; m++)
#pragma unroll
        for (int n = 0; n < 8; n++)
#pragma unroll
            for (int c = 0; c < 4; c++) acc[m][n][c] = 0.f;

    float4 a0, a1;
    float bv[8];
    a0 = *(const float4*)(pA);
    a1 = *(const float4*)(pA + 4);
#pragma unroll
    for (int c = 0; c < 8; c++) bv[c] = pB[16 * c];

    {
        uint32_t hp[4], lp[4];
        split2_pack(a0.x, a0.y, hp[0], lp[0]);
        split2_pack(a0.z, a0.w, hp[1], lp[1]);
        split2_pack(a1.x, a1.y, hp[2], lp[2]);
        split2_pack(a1.z, a1.w, hp[3], lp[3]);
        *(uint4*)&s.Ah[0][ar * KP2 + akc] = make_uint4(hp[0], hp[1], hp[2], hp[3]);
        *(uint4*)&s.Al[0][ar * KP2 + akc] = make_uint4(lp[0], lp[1], lp[2], lp[3]);
#pragma unroll
        for (int c = 0; c < 8; c++) {
            __nv_bfloat16 hh, ll;
            split_bf16(bv[c], hh, ll);
            s.Bh[0][(nb + 16 * c) * KP2 + br] = hh;
            s.Bl[0][(nb + 16 * c) * KP2 + br] = ll;
        }
    }
    __syncthreads();

    const uint32_t sAh0 = smem_to_u32(s.Ah[0]), sAl0 = smem_to_u32(s.Al[0]);
    const uint32_t sBh0 = smem_to_u32(s.Bh[0]), sBl0 = smem_to_u32(s.Bl[0]);
    const uint32_t bufStride = (uint32_t)T2 * 2;

    for (int kt = 0; kt < 32; kt++) {
        const int buf = kt & 1;
        const bool more = kt < 31;
        if (more) {
            const int k0 = (kt + 1) * 16;
            a0 = *(const float4*)(pA + k0);
            a1 = *(const float4*)(pA + k0 + 4);
#pragma unroll
            for (int c = 0; c < 8; c++) bv[c] = pB[(size_t)k0 * wld + 16 * c];
        }

        GEMM_COMPUTE(buf * bufStride)

        if (more) {
            const int nbuf = buf ^ 1;
            uint32_t hp[4], lp[4];
            split2_pack(a0.x, a0.y, hp[0], lp[0]);
            split2_pack(a0.z, a0.w, hp[1], lp[1]);
            split2_pack(a1.x, a1.y, hp[2], lp[2]);
            split2_pack(a1.z, a1.w, hp[3], lp[3]);
            *(uint4*)&s.Ah[nbuf][ar * KP2 + akc] = make_uint4(hp[0], hp[1], hp[2], hp[3]);
            *(uint4*)&s.Al[nbuf][ar * KP2 + akc] = make_uint4(lp[0], lp[1], lp[2], lp[3]);
#pragma unroll
            for (int c = 0; c < 8; c++) {
                __nv_bfloat16 hh, ll;
                split_bf16(bv[c], hh, ll);
                s.Bh[nbuf][(nb + 16 * c) * KP2 + br] = hh;
                s.Bl[nbuf][(nb + 16 * c) * KP2 + br] = ll;
            }
            __syncthreads();
        }
    }

    // ---- epilogue: split-store bf16 hi/lo into q/k/v [b,h,n,d] ----
    const int g = lane >> 2, tg = lane & 3;
    const int cbase = col0 + 64 * wc;
    __nv_bfloat16 *dhi, *dlo; int cc0;
    if (cbase < 512)       { dhi = g_qh; dlo = g_ql; cc0 = cbase; }
    else if (cbase < 1024) { dhi = g_kh; dlo = g_kl; cc0 = cbase - 512; }
    else                   { dhi = g_vh; dlo = g_vl; cc0 = cbase - 1024; }
    const int hh = cc0 >> 6;
#pragma unroll
    for (int m = 0; m < 2; m++) {
        const int rA = row0 + 32 * wr + 16 * m + g;
        const int rB = rA + 8;
        const size_t oA = ((size_t)((rA >> 10) * NUM_H + hh) * NUM_N + (rA & 1023)) * DHEAD;
        const size_t oB = ((size_t)((rB >> 10) * NUM_H + hh) * NUM_N + (rB & 1023)) * DHEAD;
#pragma unroll
        for (int n = 0; n < 8; n++) {
            const int d = n * 8 + tg * 2;
            split2_store(acc[m][n][0], acc[m][n][1], dhi + oA + d, dlo + oA + d);
            split2_store(acc[m][n][2], acc[m][n][3], dhi + oB + d, dlo + oB + d);
        }
    }
}

// ===========================================================================
// Kernel 1b: bias transpose  [b][i][j][h] -> [b][h][i][j]  (verbatim)
// ===========================================================================
__global__ __launch_bounds__(256) void bias_transpose_kernel(const float* __restrict__ in)
{
    __shared__ float sm[8 * 32 * 33];
    const int tid = threadIdx.x;
    const int j0 = blockIdx.x * 32;
    const int i0 = blockIdx.y * 32;
    const int b  = blockIdx.z;
#pragma unroll
    for (int k = 0; k < 8; k++) {
        const int idx = tid + k * 256;
        const int ii = idx >> 6;
        const int f  = idx & 63;
        const float4 v = *reinterpret_cast<const float4*>(
            in + (((size_t)b * NUM_N + i0 + ii) * NUM_N + j0) * NUM_H + f * 4);
        const int jj = f >> 1;
        const int h0 = (f & 1) * 4;
        sm[(h0 + 0) * (32 * 33) + ii * 33 + jj] = v.x;
        sm[(h0 + 1) * (32 * 33) + ii * 33 + jj] = v.y;
        sm[(h0 + 2) * (32 * 33) + ii * 33 + jj] = v.z;
        sm[(h0 + 3) * (32 * 33) + ii * 33 + jj] = v.w;
    }
    __syncthreads();
#pragma unroll
    for (int k = 0; k < 8; k++) {
        const int idx = tid + k * 256;
        const int rowid = idx >> 3;
        const int h  = rowid >> 5;
        const int ii = rowid & 31;
        const int jj0 = (idx & 7) * 4;
        float4 v;
        v.x = sm[h * (32 * 33) + ii * 33 + jj0 + 0];
        v.y = sm[h * (32 * 33) + ii * 33 + jj0 + 1];
        v.z = sm[h * (32 * 33) + ii * 33 + jj0 + 2];
        v.w = sm[h * (32 * 33) + ii * 33 + jj0 + 3];
        *reinterpret_cast<float4*>(
            g_biasT + (((size_t)(b * NUM_H + h) * NUM_N) + i0 + ii) * NUM_N + j0 + jj0) = v;
    }
}

// ===========================================================================
// Kernel 2: warp-MMA flash attention — pre-split inputs, copy-only staging.
// ===========================================================================
#define AT_QHI  0
#define AT_QLO  18432
#define AT_KHI  36864
#define AT_KLO  46080
#define AT_VHI  55296
#define AT_VLO  64512
#define AT_MK   73728
#define AT_TOTAL 73984
#define PAD 72

__global__ __launch_bounds__(128) void attn_mma_kernel(const int* __restrict__ mask)
{
    extern __shared__ char smem[];
    const uint32_t sb = smem_to_u32(smem);
    const int tid  = threadIdx.x;
    const int lane = tid & 31;
    const int w    = tid >> 5;
    const int i0   = blockIdx.x * 128;
    const int h    = blockIdx.y;
    const int bz   = blockIdx.z;

    // ---- stage Q (pure copies) ----
    {
        const size_t qb = ((size_t)(bz * NUM_H + h) * NUM_N + i0 + tid) * DHEAD;
#pragma unroll
        for (int u = 0; u < 8; u++) {
            *(uint4*)(smem + AT_QHI + (uint32_t)(tid * PAD + u * 8) * 2) = *(const uint4*)(g_qh + qb + u * 8);
            *(uint4*)(smem + AT_QLO + (uint32_t)(tid * PAD + u * 8) * 2) = *(const uint4*)(g_ql + qb + u * 8);
        }
    }

    const int g  = lane >> 2;
    const int tg = lane & 3;
    const int arow = (lane & 15);
    const int acol = (lane >> 4) * 8;
    const int brow = (lane & 7);
    const int bcol = ((lane >> 3) & 1) * 8;

    float O[2][8][4];
#pragma unroll
    for (int m = 0; m < 2; m++)
#pragma unroll
        for (int n = 0; n < 8; n++)
#pragma unroll
            for (int c = 0; c < 4; c++) O[m][n][c] = 0.f;
    float lsum[2][2] = {{0.f, 0.f}, {0.f, 0.f}};

    const int krow = tid >> 1;
    const int kch  = (tid & 1) * 32;
    float* mk = reinterpret_cast<float*>(smem + AT_MK);

    for (int jt = 0; jt < 16; jt++) {
        const int j0 = jt * 64;
        __syncthreads();

        // ---- stage K, V (pure copies) ----
        {
            const size_t base = ((size_t)(bz * NUM_H + h) * NUM_N + j0 + krow) * DHEAD + kch;
            const uint32_t so = (uint32_t)(krow * PAD + kch) * 2;
#pragma unroll
            for (int u = 0; u < 4; u++) {
                *(uint4*)(smem + AT_KHI + so + u * 16) = *(const uint4*)(g_kh + base + u * 8);
                *(uint4*)(smem + AT_KLO + so + u * 16) = *(const uint4*)(g_kl + base + u * 8);
                *(uint4*)(smem + AT_VHI + so + u * 16) = *(const uint4*)(g_vh + base + u * 8);
                *(uint4*)(smem + AT_VLO + so + u * 16) = *(const uint4*)(g_vl + base + u * 8);
            }
        }
        if (tid < 64) mk[tid] = mask[bz * NUM_N + j0 + tid] ? 1.f : 0.f;
        __syncthreads();

        // ---- S = Q K^T (3 split terms, m-interleaved) ----
        float S[2][8][4];
#pragma unroll
        for (int m = 0; m < 2; m++)
#pragma unroll
            for (int n = 0; n < 8; n++)
#pragma unroll
                for (int c = 0; c < 4; c++) S[m][n][c] = 0.f;

#pragma unroll
        for (int ks = 0; ks < 4; ks++) {
            uint32_t ah[2][4], al[2][4];
#pragma unroll
            for (int m = 0; m < 2; m++) {
                const uint32_t aoff = sb + AT_QHI +
                    (uint32_t)((32 * w + 16 * m + arow) * PAD + ks * 16 + acol) * 2;
                ldmx4(ah[m], aoff);
                ldmx4(al[m], aoff + (AT_QLO - AT_QHI));
            }
#pragma unroll
            for (int n = 0; n < 8; n++) {
                uint32_t bh[2], bl[2];
                const uint32_t boff = sb + AT_KHI +
                    (uint32_t)((n * 8 + brow) * PAD + ks * 16 + bcol) * 2;
                ldmx2(bh, boff);
                ldmx2(bl, boff + (AT_KLO - AT_KHI));
                mma16816(S[0][n], ah[0], bh);
                mma16816(S[1][n], ah[1], bh);
                mma16816(S[0][n], al[0], bh);
                mma16816(S[1][n], al[1], bh);
                mma16816(S[0][n], ah[0], bl);
                mma16816(S[1][n], ah[1], bl);
            }
        }

        // ---- softmax -> P fragments (registers only) ----
        uint32_t ph[2][4][4], pl[2][4][4];
#pragma unroll
        for (int m = 0; m < 2; m++) {
            const int r1 = i0 + 32 * w + 16 * m + g;
            const float* bp1 = g_biasT + ((size_t)(bz * NUM_H + h) * NUM_N + r1) * NUM_N + j0 + tg * 2;
            const float* bp2 = bp1 + 8 * NUM_N;
#pragma unroll
            for (int n = 0; n < 8; n++) {
                const float2 bb1 = *reinterpret_cast<const float2*>(bp1 + n * 8);
                const float2 bb2 = *reinterpret_cast<const float2*>(bp2 + n * 8);
                const float2 mm  = *reinterpret_cast<const float2*>(mk + n * 8 + tg * 2);
                const float p0 = mm.x * __expf(fmaf(S[m][n][0], QK_SCALE, bb1.x));
                const float p1 = mm.y * __expf(fmaf(S[m][n][1], QK_SCALE, bb1.y));
                const float p2 = mm.x * __expf(fmaf(S[m][n][2], QK_SCALE, bb2.x));
                const float p3 = mm.y * __expf(fmaf(S[m][n][3], QK_SCALE, bb2.y));
                lsum[m][0] += p0 + p1;
                lsum[m][1] += p2 + p3;
                const int kc = n >> 1;
                const int rb = (n & 1) * 2;
                __nv_bfloat16 hx, lx, hy, ly;
                split_bf16(p0, hx, lx); split_bf16(p1, hy, ly);
                ph[m][kc][rb]   = packbf2(__bfloat162float(hx), __bfloat162float(hy));
                pl[m][kc][rb]   = packbf2(__bfloat162float(lx), __bfloat162float(ly));
                split_bf16(p2, hx, lx); split_bf16(p3, hy, ly);
                ph[m][kc][rb+1] = packbf2(__bfloat162float(hx), __bfloat162float(hy));
                pl[m][kc][rb+1] = packbf2(__bfloat162float(lx), __bfloat162float(ly));
            }
        }

        // ---- O += P V (3 split terms, m-interleaved) ----
#pragma unroll
        for (int kc = 0; kc < 4; kc++) {
#pragma unroll
            for (int n = 0; n < 8; n++) {
                uint32_t vh[2], vl[2];
                const uint32_t voff = sb + AT_VHI +
                    (uint32_t)((kc * 16 + (lane & 15)) * PAD + n * 8) * 2;
                ldmx2t(vh, voff);
                ldmx2t(vl, voff + (AT_VLO - AT_VHI));
                mma16816(O[0][n], ph[0][kc], vh);
                mma16816(O[1][n], ph[1][kc], vh);
                mma16816(O[0][n], ph[0][kc], vl);
                mma16816(O[1][n], ph[1][kc], vl);
                mma16816(O[0][n], pl[0][kc], vh);
                mma16816(O[1][n], pl[1][kc], vh);
            }
        }
    }

    // ---- epilogue ----
#pragma unroll
    for (int m = 0; m < 2; m++)
#pragma unroll
        for (int r = 0; r < 2; r++) {
            lsum[m][r] += __shfl_xor_sync(0xffffffffu, lsum[m][r], 1);
            lsum[m][r] += __shfl_xor_sync(0xffffffffu, lsum[m][r], 2);
        }
#pragma unroll
    for (int m = 0; m < 2; m++) {
        const int r1 = i0 + 32 * w + 16 * m + g;
        const float inv1 = 1.f / lsum[m][0];
        const float inv2 = 1.f / lsum[m][1];
        float* o1 = g_att + ((size_t)bz * NUM_N + r1) * DINNER + h * DHEAD + tg * 2;
        float* o2 = o1 + 8 * DINNER;
#pragma unroll
        for (int n = 0; n < 8; n++) {
            *reinterpret_cast<float2*>(o1 + n * 8) = make_float2(O[m][n][0] * inv1, O[m][n][1] * inv1);
            *reinterpret_cast<float2*>(o2 + n * 8) = make_float2(O[m][n][2] * inv2, O[m][n][3] * inv2);
        }
    }
}

// ===========================================================================
// Kernel 3: output projection (double-buffered, term-major MMA)
// ===========================================================================
__global__ __launch_bounds__(256) void out_mma_kernel(
    const float* __restrict__ Wout, const float* __restrict__ bout, float* __restrict__ out)
{
    __shared__ GemmSmem2 s;
    const int tid = threadIdx.x, lane = tid & 31, w = tid >> 5;
    const int wr = w >> 1, wc = w & 1;
    const int row0 = blockIdx.y * 128, col0 = blockIdx.x * 128;

    const int ar = tid >> 1, akc = (tid & 1) * 8;
    const float* pA = g_att + (size_t)(row0 + ar) * DINNER + akc;
    const int br = tid >> 4, nb = tid & 15;
    const float* pB = Wout + (size_t)br * DOUT + col0 + nb;

    float acc[2][8][4];
#pragma unroll
    for (int m = 0; m < 2; m++)
#pragma unroll
        for (int n = 0; n < 8; n++)
#pragma unroll
            for (int c = 0; c < 4; c++) acc[m][n][c] = 0.f;

    float4 a0, a1;
    float bv[8];
    a0 = *(const float4*)(pA);
    a1 = *(const float4*)(pA + 4);
#pragma unroll
    for (int c = 0; c < 8; c++) bv[c] = pB[16 * c];

    {
        uint32_t hp[4], lp[4];
        split2_pack(a0.x, a0.y, hp[0], lp[0]);
        split2_pack(a0.z, a0.w, hp[1], lp[1]);
        split2_pack(a1.x, a1.y, hp[2], lp[2]);
        split2_pack(a1.z, a1.w, hp[3], lp[3]);
        *(uint4*)&s.Ah[0][ar * KP2 + akc] = make_uint4(hp[0], hp[1], hp[2], hp[3]);
        *(uint4*)&s.Al[0][ar * KP2 + akc] = make_uint4(lp[0], lp[1], lp[2], lp[3]);
#pragma unroll
        for (int c = 0; c < 8; c++) {
            __nv_bfloat16 hh, ll;
            split_bf16(bv[c], hh, ll);
            s.Bh[0][(nb + 16 * c) * KP2 + br] = hh;
            s.Bl[0][(nb + 16 * c) * KP2 + br] = ll;
        }
    }
    __syncthreads();

    const uint32_t sAh0 = smem_to_u32(s.Ah[0]), sAl0 = smem_to_u32(s.Al[0]);
    const uint32_t sBh0 = smem_to_u32(s.Bh[0]), sBl0 = smem_to_u32(s.Bl[0]);
    const uint32_t bufStride = (uint32_t)T2 * 2;

    for (int kt = 0; kt < 32; kt++) {
        const int buf = kt & 1;
        const bool more = kt < 31;
        if (more) {
            const int k0 = (kt + 1) * 16;
            a0 = *(const float4*)(pA + k0);
            a1 = *(const float4*)(pA + k0 + 4);
#pragma unroll
            for (int c = 0; c < 8; c++) bv[c] = pB[(size_t)k0 * DOUT + 16 * c];
        }

        GEMM_COMPUTE(buf * bufStride)

        if (more) {
            const int nbuf = buf ^ 1;
            uint32_t hp[4], lp[4];
            split2_pack(a0.x, a0.y, hp[0], lp[0]);
            split2_pack(a0.z, a0.w, hp[1], lp[1]);
            split2_pack(a1.x, a1.y, hp[2], lp[2]);
            split2_pack(a1.z, a1.w, hp[3], lp[3]);
            *(uint4*)&s.Ah[nbuf][ar * KP2 + akc] = make_uint4(hp[0], hp[1], hp[2], hp[3]);
            *(uint4*)&s.Al[nbuf][ar * KP2 + akc] = make_uint4(lp[0], lp[1], lp[2], lp[3]);
#pragma unroll
            for (int c = 0; c < 8; c++) {
                __nv_bfloat16 hh, ll;
                split_bf16(bv[c], hh, ll);
                s.Bh[nbuf][(nb + 16 * c) * KP2 + br] = hh;
                s.Bl[nbuf][(nb + 16 * c) * KP2 + br] = ll;
            }
            __syncthreads();
        }
    }

    const int g = lane >> 2, tg = lane & 3;
#pragma unroll
    for (int m = 0; m < 2; m++) {
        const int rA = row0 + 32 * wr + 16 * m + g;
        const int rB = rA + 8;
#pragma unroll
        for (int n = 0; n < 8; n++) {
            const int c = col0 + 64 * wc + n * 8 + tg * 2;
            const float2 bv2 = *reinterpret_cast<const float2*>(bout + c);
            *reinterpret_cast<float2*>(out + (size_t)rA * DOUT + c) =
                make_float2(acc[m][n][0] + bv2.x, acc[m][n][1] + bv2.y);
            *reinterpret_cast<float2*>(out + (size_t)rB * DOUT + c) =
                make_float2(acc[m][n][2] + bv2.x, acc[m][n][3] + bv2.y);
        }
    }
}

// ---------------------------------------------------------------------------
extern "C" void kernel_launch(void* const* d_in, const int* in_sizes, int n_in,
                              void* d_out, int out_size)
{
    const float* x    = (const float*)d_in[0];
    const int*   mask = (const int*)  d_in[1];
    const float* sb   = (const float*)d_in[2];
    const float* Wq   = (const float*)d_in[3];
    const float* Wkv  = (const float*)d_in[4];
    const float* Wout = (const float*)d_in[5];
    const float* bout = (const float*)d_in[6];
    float* out = (float*)d_out;

    // 1) QKV projection (double-buffered, term-major MMA, bf16 hi/lo outputs)
    qkv_mma_kernel<<<dim3(12, 64), 256>>>(x, Wq, Wkv);

    // 1b) bias transpose
    bias_transpose_kernel<<<dim3(32, 32, NUM_B), 256>>>(sb);

    // 2) warp-MMA flash attention (copy-only staging)
    cudaFuncSetAttribute(attn_mma_kernel, cudaFuncAttributeMaxDynamicSharedMemorySize, AT_TOTAL);
    attn_mma_kernel<<<dim3(NUM_N / 128, NUM_H, NUM_B), 128, AT_TOTAL>>>(mask);

    // 3) output projection (double-buffered, term-major MMA)
    out_mma_kernel<<<dim3(4, 64), 256>>>(Wout, bout, out);
}